// round 1
// baseline (speedup 1.0000x reference)
#include <cuda_runtime.h>

// HMM-VAE fused pipeline.
// Shapes: B=32, T=128, N=B*T=4096, K=16 (HMM states), L=16 (latent), D=784, H=400.
//
// Inputs (metadata order):
//  0 y_batch  [32,128,1,28,28] -> y_flat [4096,784]
//  1 enc_w1   [400,784]
//  2 enc_b1   [400]
//  3 enc_w2   [32,400]
//  4 enc_b2   [32]
//  5 dec_fc_w [400,32]
//  6 dec_fc_b [400]
//  7 dec_w    [784,400]
//  8 dec_b    [784]
//  9 log_pi   [16]
// 10 log_A    [16,16]
// 11 eps      [4096,16]
// Output: gamma [32,128,16] (65536) then xi [32,127,16,16] (1040384), fp32.

#define N_TOT 4096
#define DH    400

// -------- scratch (static device globals; no allocation) --------
__device__ float g_H[N_TOT * DH];       // encoder hidden
__device__ float g_base[N_TOT * DH];    // z @ Wz.T + fcb
__device__ float g_logb[N_TOT * 16];    // log_bk, [n][k], n = b*128+t
__device__ float g_la[32 * 128 * 16];   // log_alpha
__device__ float g_lbeta[32 * 128 * 16];// log_beta

// ============================================================================
// Kernel A: H = relu(Y @ W1^T + b1)    [4096,400] = [4096,784] x [400,784]^T
// Tiles: 128 n x 64 h, KT=16 (784 = 49*16). grid (32, 7), 256 threads.
// ============================================================================
__global__ __launch_bounds__(256) void k_enc1(const float* __restrict__ y,
                                              const float* __restrict__ w1,
                                              const float* __restrict__ b1) {
    __shared__ __align__(16) float As[16 * 132];  // [kt][n], padded
    __shared__ __align__(16) float Bs[16 * 68];   // [kt][h], padded
    const int tid = threadIdx.x;
    const int tx = tid & 15, ty = tid >> 4;
    const int n0 = blockIdx.x * 128;
    const int h0 = blockIdx.y * 64;

    float acc[8][4];
#pragma unroll
    for (int i = 0; i < 8; i++)
#pragma unroll
        for (int j = 0; j < 4; j++) acc[i][j] = 0.f;

    for (int kt = 0; kt < 49; kt++) {
        const int o0 = kt * 16;
        // A tile: 128 x 16 from y
#pragma unroll
        for (int rr = 0; rr < 8; rr++) {
            int r = ty + rr * 16;
            As[tx * 132 + r] = y[(n0 + r) * 784 + o0 + tx];
        }
        // B tile: 64 x 16 from w1 (guard h<400)
#pragma unroll
        for (int rr = 0; rr < 4; rr++) {
            int r = ty + rr * 16;
            int hh = h0 + r;
            Bs[tx * 68 + r] = (hh < 400) ? w1[hh * 784 + o0 + tx] : 0.f;
        }
        __syncthreads();
#pragma unroll
        for (int h = 0; h < 16; h++) {
            float4 a0 = *(const float4*)&As[h * 132 + ty * 8];
            float4 a1 = *(const float4*)&As[h * 132 + ty * 8 + 4];
            float4 bb = *(const float4*)&Bs[h * 68 + tx * 4];
            float a[8] = {a0.x, a0.y, a0.z, a0.w, a1.x, a1.y, a1.z, a1.w};
            float bv[4] = {bb.x, bb.y, bb.z, bb.w};
#pragma unroll
            for (int i = 0; i < 8; i++)
#pragma unroll
                for (int j = 0; j < 4; j++) acc[i][j] = fmaf(a[i], bv[j], acc[i][j]);
        }
        __syncthreads();
    }
#pragma unroll
    for (int j = 0; j < 4; j++) {
        int h = h0 + tx * 4 + j;
        if (h < 400) {
            float bias = b1[h];
#pragma unroll
            for (int i = 0; i < 8; i++) {
                int n = n0 + ty * 8 + i;
                g_H[n * 400 + h] = fmaxf(acc[i][j] + bias, 0.f);
            }
        }
    }
}

// ============================================================================
// Kernel BC: encoder2 + reparam + base.
// grid 256 (16 n each), 256 threads.
// ============================================================================
__global__ __launch_bounds__(256) void k_enc2_base(const float* __restrict__ w2,
                                                   const float* __restrict__ b2,
                                                   const float* __restrict__ fcw,
                                                   const float* __restrict__ fcb,
                                                   const float* __restrict__ eps) {
    __shared__ float sh[6400];    // phase1: Hs [16][400];  phase2: Wzs [400][16]
    __shared__ float shW[1600];   // W2 chunk [32][50]
    __shared__ float zs[256];     // z [16][16]
    const int tid = threadIdx.x;
    const int n0 = blockIdx.x * 16;

    // stage H rows
#pragma unroll
    for (int ii = 0; ii < 25; ii++) {
        int idx = tid + ii * 256;
        sh[idx] = g_H[n0 * 400 + idx];
    }
    const int nl = tid >> 4, l = tid & 15;
    float mu = 0.f, lv = 0.f;
    for (int ch = 0; ch < 8; ch++) {
        __syncthreads();
        for (int idx = tid; idx < 1600; idx += 256) {
            int row = idx / 50, col = idx % 50;
            shW[idx] = w2[row * 400 + ch * 50 + col];
        }
        __syncthreads();
#pragma unroll
        for (int hh = 0; hh < 50; hh++) {
            float hv = sh[nl * 400 + ch * 50 + hh];
            mu = fmaf(hv, shW[l * 50 + hh], mu);
            lv = fmaf(hv, shW[(16 + l) * 50 + hh], lv);
        }
    }
    mu += b2[l];
    lv += b2[16 + l];
    float z = mu + eps[(n0 + nl) * 16 + l] * __expf(0.5f * lv);
    zs[nl * 16 + l] = z;
    __syncthreads();
    // stage Wz [400][16] (overwrites Hs region)
#pragma unroll
    for (int ii = 0; ii < 25; ii++) {
        int idx = tid + ii * 256;
        int h = idx >> 4, ll = idx & 15;
        sh[idx] = fcw[h * 32 + ll];
    }
    __syncthreads();
#pragma unroll
    for (int ii = 0; ii < 25; ii++) {
        int idx = tid + ii * 256;
        int nn = idx / 400, h = idx % 400;
        float s = fcb[h];
#pragma unroll
        for (int ll = 0; ll < 16; ll++) s = fmaf(zs[nn * 16 + ll], sh[h * 16 + ll], s);
        g_base[(n0 + nn) * 400 + h] = s;
    }
}

// ============================================================================
// Kernel D: per-state decoder GEMM fused with BCE reduction.
// log_bk[n][k] = -(sum_o bce(sigmoid(relu(base+wx_k) @ dec_w^T + db), y)) / 100
// grid (32 ntiles, 16 k), 256 threads. 128 n x 64 o tile, o-tiles looped inside.
// ============================================================================
__global__ __launch_bounds__(256) void k_dec_bce(const float* __restrict__ fcw,
                                                 const float* __restrict__ dw,
                                                 const float* __restrict__ db,
                                                 const float* __restrict__ y) {
    __shared__ __align__(16) float As[16 * 132];  // hk tile [kt][n]
    __shared__ __align__(16) float Bs[16 * 68];   // dec_w tile [kt][o]
    __shared__ float wxs[400];
    __shared__ float red[128 * 17];
    const int tid = threadIdx.x;
    const int tx = tid & 15, ty = tid >> 4;
    const int n0 = blockIdx.x * 128;
    const int k = blockIdx.y;

    for (int h = tid; h < 400; h += 256) wxs[h] = fcw[h * 32 + 16 + k];
    __syncthreads();

    float bsum[8];
#pragma unroll
    for (int i = 0; i < 8; i++) bsum[i] = 0.f;

    for (int ot = 0; ot < 13; ot++) {
        const int o0 = ot * 64;
        float acc[8][4];
#pragma unroll
        for (int i = 0; i < 8; i++)
#pragma unroll
            for (int j = 0; j < 4; j++) acc[i][j] = 0.f;

        for (int kt = 0; kt < 25; kt++) {
            const int h0 = kt * 16;
#pragma unroll
            for (int rr = 0; rr < 8; rr++) {
                int r = ty + rr * 16;
                float v = g_base[(n0 + r) * 400 + h0 + tx] + wxs[h0 + tx];
                As[tx * 132 + r] = fmaxf(v, 0.f);
            }
#pragma unroll
            for (int rr = 0; rr < 4; rr++) {
                int r = ty + rr * 16;
                int o = o0 + r;
                Bs[tx * 68 + r] = (o < 784) ? dw[o * 400 + h0 + tx] : 0.f;
            }
            __syncthreads();
#pragma unroll
            for (int h = 0; h < 16; h++) {
                float4 a0 = *(const float4*)&As[h * 132 + ty * 8];
                float4 a1 = *(const float4*)&As[h * 132 + ty * 8 + 4];
                float4 bb = *(const float4*)&Bs[h * 68 + tx * 4];
                float a[8] = {a0.x, a0.y, a0.z, a0.w, a1.x, a1.y, a1.z, a1.w};
                float bv[4] = {bb.x, bb.y, bb.z, bb.w};
#pragma unroll
                for (int i = 0; i < 8; i++)
#pragma unroll
                    for (int j = 0; j < 4; j++) acc[i][j] = fmaf(a[i], bv[j], acc[i][j]);
            }
            __syncthreads();
        }
        // BCE epilogue. 784 = 12*64+16 so the last tile is all-or-nothing per
        // float4 column group (tx<4 valid, tx>=4 fully out of range).
        bool valid = (o0 + tx * 4 + 3) < 784;
        if (valid) {
            float bias[4];
#pragma unroll
            for (int j = 0; j < 4; j++) bias[j] = db[o0 + tx * 4 + j];
#pragma unroll
            for (int i = 0; i < 8; i++) {
                int n = n0 + ty * 8 + i;
                float4 yv = *(const float4*)&y[n * 784 + o0 + tx * 4];
                float ya[4] = {yv.x, yv.y, yv.z, yv.w};
                float bacc = 0.f;
#pragma unroll
                for (int j = 0; j < 4; j++) {
                    float x = acc[i][j] + bias[j];
                    // softplus(x) = max(x,0)+log1p(exp(-|x|)); softplus(-x)=sp-x
                    float sp = fmaxf(x, 0.f) + __logf(1.f + __expf(-fabsf(x)));
                    float t1 = fminf(sp - x, 100.f);  // -log(yrec), clipped
                    float t2 = fminf(sp, 100.f);      // -log(1-yrec), clipped
                    bacc += ya[j] * t1 + (1.f - ya[j]) * t2;
                }
                bsum[i] += bacc;
            }
        }
    }
    // reduce over tx (o-groups)
#pragma unroll
    for (int i = 0; i < 8; i++) red[(ty * 8 + i) * 17 + tx] = bsum[i];
    __syncthreads();
    if (tid < 128) {
        float s = 0.f;
#pragma unroll
        for (int t2 = 0; t2 < 16; t2++) s += red[tid * 17 + t2];
        g_logb[(n0 + tid) * 16 + k] = -s * 0.01f;
    }
}

// ============================================================================
// Kernel E: HMM forward/backward + gamma. One block per batch b. 256 threads.
// ============================================================================
__global__ __launch_bounds__(256) void k_hmm(const float* __restrict__ log_pi,
                                             const float* __restrict__ log_A,
                                             float* __restrict__ out) {
    __shared__ float lbs[2048];   // log_bk [t][k]
    __shared__ float sA[256];     // log(softmax(log_A)+1e-9) [j][k]
    __shared__ float lp[16];
    __shared__ float as[2048];    // log_alpha
    __shared__ float bs[2048];    // log_beta
    __shared__ float p0[16], p1[16], q0[16], q1[16];
    const int b = blockIdx.x;
    const int tid = threadIdx.x;
    const unsigned FULL = 0xffffffffu;

#pragma unroll
    for (int ii = 0; ii < 8; ii++) {
        int idx = tid + ii * 256;
        lbs[idx] = g_logb[b * 2048 + idx];
    }
    // normalized transition logs (rows of log_A)
    {
        float v = log_A[tid];  // tid = j*16 + k, k minor in lanes
        float m = v;
#pragma unroll
        for (int mk = 8; mk >= 1; mk >>= 1) m = fmaxf(m, __shfl_xor_sync(FULL, m, mk));
        float e = expf(v - m);
        float s = e;
#pragma unroll
        for (int mk = 8; mk >= 1; mk >>= 1) s += __shfl_xor_sync(FULL, s, mk);
        sA[tid] = logf(e / s + 1e-9f);
    }
    if (tid < 16) {
        float v = log_pi[tid];
        float m = v;
#pragma unroll
        for (int mk = 8; mk >= 1; mk >>= 1) m = fmaxf(m, __shfl_xor_sync(0xffffu, m, mk));
        float e = expf(v - m);
        float s = e;
#pragma unroll
        for (int mk = 8; mk >= 1; mk >>= 1) s += __shfl_xor_sync(0xffffu, s, mk);
        lp[tid] = logf(e / s + 1e-9f);
    }
    __syncthreads();
    if (tid < 16) {
        float a = lp[tid] + lbs[tid];
        as[tid] = a;
        p0[tid] = a;
    }
    __syncthreads();
    // forward: thread (k = tid>>4, j = tid&15); reduce over j (lane-minor)
    {
        const int k = tid >> 4, j = tid & 15;
        for (int t = 1; t < 128; t++) {
            const float* src = (t & 1) ? p0 : p1;
            float* dst = (t & 1) ? p1 : p0;
            float v = src[j] + sA[j * 16 + k];
            float m = v;
#pragma unroll
            for (int mk = 8; mk >= 1; mk >>= 1) m = fmaxf(m, __shfl_xor_sync(FULL, m, mk));
            float e = expf(v - m);
            float s = e;
#pragma unroll
            for (int mk = 8; mk >= 1; mk >>= 1) s += __shfl_xor_sync(FULL, s, mk);
            float cur = m + logf(s) + lbs[t * 16 + k];
            if (j == 0) { as[t * 16 + k] = cur; dst[k] = cur; }
            __syncthreads();
        }
    }
    // backward: thread (j = tid>>4, k = tid&15); reduce over k (lane-minor)
    if (tid < 16) { bs[127 * 16 + tid] = 0.f; q1[tid] = 0.f; }
    __syncthreads();
    {
        const int j = tid >> 4, k = tid & 15;
        for (int t = 126; t >= 0; t--) {
            const float* src = ((t + 1) & 1) ? q1 : q0;
            float* dst = (t & 1) ? q1 : q0;
            float v = sA[j * 16 + k] + lbs[(t + 1) * 16 + k] + src[k];
            float m = v;
#pragma unroll
            for (int mk = 8; mk >= 1; mk >>= 1) m = fmaxf(m, __shfl_xor_sync(FULL, m, mk));
            float e = expf(v - m);
            float s = e;
#pragma unroll
            for (int mk = 8; mk >= 1; mk >>= 1) s += __shfl_xor_sync(FULL, s, mk);
            float cur = m + logf(s);
            if (k == 0) { bs[t * 16 + j] = cur; dst[j] = cur; }
            __syncthreads();
        }
    }
    // spill alpha/beta for the xi kernel
#pragma unroll
    for (int ii = 0; ii < 8; ii++) {
        int idx = tid + ii * 256;
        g_la[b * 2048 + idx] = as[idx];
        g_lbeta[b * 2048 + idx] = bs[idx];
    }
    // gamma
    if (tid < 128) {
        int t = tid;
        float lg[16];
        float m = -1e30f;
#pragma unroll
        for (int kk = 0; kk < 16; kk++) {
            lg[kk] = as[t * 16 + kk] + bs[t * 16 + kk];
            m = fmaxf(m, lg[kk]);
        }
        float s = 0.f;
#pragma unroll
        for (int kk = 0; kk < 16; kk++) s += expf(lg[kk] - m);
        float l = m + logf(s);
#pragma unroll
        for (int kk = 0; kk < 16; kk++) out[b * 2048 + t * 16 + kk] = expf(lg[kk] - l);
    }
}

// ============================================================================
// Kernel F: xi. grid (127, 32), 256 threads; block-wide logsumexp over (j,k).
// ============================================================================
__global__ __launch_bounds__(256) void k_xi(const float* __restrict__ log_A,
                                            float* __restrict__ out) {
    __shared__ float sA[256];
    __shared__ float wm[8], ws[8];
    const int t = blockIdx.x;   // 0..126
    const int b = blockIdx.y;
    const int tid = threadIdx.x;
    const int j = tid >> 4, k = tid & 15;
    const unsigned FULL = 0xffffffffu;
    {
        float v = log_A[tid];
        float m = v;
#pragma unroll
        for (int mk = 8; mk >= 1; mk >>= 1) m = fmaxf(m, __shfl_xor_sync(FULL, m, mk));
        float e = expf(v - m);
        float s = e;
#pragma unroll
        for (int mk = 8; mk >= 1; mk >>= 1) s += __shfl_xor_sync(FULL, s, mk);
        sA[tid] = logf(e / s + 1e-9f);
    }
    __syncthreads();
    const int nt = b * 128 + t;
    float v = g_la[nt * 16 + j] + sA[tid] + g_logb[(nt + 1) * 16 + k] + g_lbeta[(nt + 1) * 16 + k];
    float m = v;
#pragma unroll
    for (int mk = 16; mk >= 1; mk >>= 1) m = fmaxf(m, __shfl_xor_sync(FULL, m, mk));
    if ((tid & 31) == 0) wm[tid >> 5] = m;
    __syncthreads();
    float M = wm[0];
#pragma unroll
    for (int w = 1; w < 8; w++) M = fmaxf(M, wm[w]);
    float e = expf(v - M);
    float s = e;
#pragma unroll
    for (int mk = 16; mk >= 1; mk >>= 1) s += __shfl_xor_sync(FULL, s, mk);
    if ((tid & 31) == 0) ws[tid >> 5] = s;
    __syncthreads();
    float S = 0.f;
#pragma unroll
    for (int w = 0; w < 8; w++) S += ws[w];
    out[65536 + (b * 127 + t) * 256 + tid] = expf(v - M - logf(S));
}

// ============================================================================
extern "C" void kernel_launch(void* const* d_in, const int* in_sizes, int n_in,
                              void* d_out, int out_size) {
    const float* y   = (const float*)d_in[0];
    const float* w1  = (const float*)d_in[1];
    const float* b1  = (const float*)d_in[2];
    const float* w2  = (const float*)d_in[3];
    const float* b2  = (const float*)d_in[4];
    const float* fcw = (const float*)d_in[5];
    const float* fcb = (const float*)d_in[6];
    const float* dw  = (const float*)d_in[7];
    const float* db  = (const float*)d_in[8];
    const float* lpi = (const float*)d_in[9];
    const float* lA  = (const float*)d_in[10];
    const float* eps = (const float*)d_in[11];
    float* out = (float*)d_out;

    k_enc1<<<dim3(32, 7), 256>>>(y, w1, b1);
    k_enc2_base<<<256, 256>>>(w2, b2, fcw, fcb, eps);
    k_dec_bce<<<dim3(32, 16), 256>>>(fcw, dw, db, y);
    k_hmm<<<32, 256>>>(lpi, lA, out);
    k_xi<<<dim3(127, 32), 256>>>(lA, out);
}

// round 3
// speedup vs baseline: 2.9273x; 2.9273x over previous
#include <cuda_runtime.h>
#include <cuda_bf16.h>
#include <stdint.h>

// HMM-VAE fused pipeline. Decoder GEMM on classic tensor cores (mma.sync bf16),
// since the harness compiles via compute_103 PTX (tcgen05 is sm_103a-only).
// B=32, T=128, N=4096, K=16, L=16, D=784, H=400.

#define N_TOT 4096

// -------- scratch (static device globals; no allocation) --------
__device__ float g_H[N_TOT * 400];
__device__ float g_base[N_TOT * 400];
__device__ float g_logb[N_TOT * 16];
__device__ float g_la[N_TOT * 16];
__device__ float g_lbeta[N_TOT * 16];
__device__ uint4 g_dwb[49 * 1008];           // dec_w bf16 slabs [ot*7+s][112 o][72 half]
__device__ float g_yt[32 * 7 * 112 * 128];   // y transposed tiles [nt][ot][o][n]

// ======================= helpers =======================
static __device__ __forceinline__ uint32_t smem_u32(const void* p) {
    uint32_t a;
    asm("{ .reg .u64 t; cvta.to.shared.u64 t, %1; cvt.u32.u64 %0, t; }" : "=r"(a) : "l"(p));
    return a;
}
static __device__ __forceinline__ void cp_async16(uint32_t saddr, const void* g) {
    asm volatile("cp.async.cg.shared.global [%0], [%1], 16;" :: "r"(saddr), "l"(g));
}
static __device__ __forceinline__ void cp_commit() {
    asm volatile("cp.async.commit_group;" ::: "memory");
}
static __device__ __forceinline__ void cp_wait0() {
    asm volatile("cp.async.wait_group 0;" ::: "memory");
}
static __device__ __forceinline__ void mma16816(float* c, const uint32_t* a, const uint32_t* b) {
    asm volatile(
        "mma.sync.aligned.m16n8k16.row.col.f32.bf16.bf16.f32 "
        "{%0,%1,%2,%3}, {%4,%5,%6,%7}, {%8,%9}, {%0,%1,%2,%3};"
        : "+f"(c[0]), "+f"(c[1]), "+f"(c[2]), "+f"(c[3])
        : "r"(a[0]), "r"(a[1]), "r"(a[2]), "r"(a[3]), "r"(b[0]), "r"(b[1]));
}
static __device__ __forceinline__ uint32_t pack_bf16x2(float a, float b) {
    __nv_bfloat162 t = __floats2bfloat162_rn(a, b);
    return *reinterpret_cast<uint32_t*>(&t);
}

// ============================================================================
// pack kernels
// ============================================================================
__global__ __launch_bounds__(256) void k_pack_dw(const float* __restrict__ dw) {
    int idx = blockIdx.x * 256 + threadIdx.x;
    if (idx >= 49 * 112 * 72) return;
    int slabIdx = idx / 8064, rem = idx % 8064;
    int o = rem / 72, c = rem % 72;
    int ot = slabIdx / 7, s = slabIdx % 7;
    int h = s * 64 + c;
    float v = (c < 64 && h < 400) ? dw[(ot * 112 + o) * 400 + h] : 0.f;
    ((__nv_bfloat16*)g_dwb)[idx] = __float2bfloat16(v);
}

__global__ __launch_bounds__(256) void k_pack_y(const float* __restrict__ y) {
    __shared__ float sm[64 * 113];
    int nt = blockIdx.x, ot = blockIdx.y, tid = threadIdx.x;
    float* outb = g_yt + (nt * 7 + ot) * 14336;
    for (int half = 0; half < 2; half++) {
        int nb = nt * 128 + half * 64;
        for (int idx = tid; idx < 64 * 112; idx += 256) {
            int nl = idx / 112, c = idx % 112;
            sm[nl * 113 + c] = y[(nb + nl) * 784 + ot * 112 + c];
        }
        __syncthreads();
        for (int idx = tid; idx < 112 * 64; idx += 256) {
            int c = idx >> 6, nl = idx & 63;
            outb[c * 128 + half * 64 + nl] = sm[nl * 113 + c];
        }
        __syncthreads();
    }
}

// ============================================================================
// Kernel A: H = relu(Y @ W1^T + b1)   (fp32 SIMT)
// ============================================================================
__global__ __launch_bounds__(256) void k_enc1(const float* __restrict__ y,
                                              const float* __restrict__ w1,
                                              const float* __restrict__ b1) {
    __shared__ __align__(16) float As[16 * 132];
    __shared__ __align__(16) float Bs[16 * 68];
    const int tid = threadIdx.x;
    const int tx = tid & 15, ty = tid >> 4;
    const int n0 = blockIdx.x * 128;
    const int h0 = blockIdx.y * 64;

    float acc[8][4];
#pragma unroll
    for (int i = 0; i < 8; i++)
#pragma unroll
        for (int j = 0; j < 4; j++) acc[i][j] = 0.f;

    for (int kt = 0; kt < 49; kt++) {
        const int o0 = kt * 16;
#pragma unroll
        for (int rr = 0; rr < 8; rr++) {
            int r = ty + rr * 16;
            As[tx * 132 + r] = y[(n0 + r) * 784 + o0 + tx];
        }
#pragma unroll
        for (int rr = 0; rr < 4; rr++) {
            int r = ty + rr * 16;
            int hh = h0 + r;
            Bs[tx * 68 + r] = (hh < 400) ? w1[hh * 784 + o0 + tx] : 0.f;
        }
        __syncthreads();
#pragma unroll
        for (int h = 0; h < 16; h++) {
            float4 a0 = *(const float4*)&As[h * 132 + ty * 8];
            float4 a1 = *(const float4*)&As[h * 132 + ty * 8 + 4];
            float4 bb = *(const float4*)&Bs[h * 68 + tx * 4];
            float a[8] = {a0.x, a0.y, a0.z, a0.w, a1.x, a1.y, a1.z, a1.w};
            float bv[4] = {bb.x, bb.y, bb.z, bb.w};
#pragma unroll
            for (int i = 0; i < 8; i++)
#pragma unroll
                for (int j = 0; j < 4; j++) acc[i][j] = fmaf(a[i], bv[j], acc[i][j]);
        }
        __syncthreads();
    }
#pragma unroll
    for (int j = 0; j < 4; j++) {
        int h = h0 + tx * 4 + j;
        if (h < 400) {
            float bias = b1[h];
#pragma unroll
            for (int i = 0; i < 8; i++) {
                int n = n0 + ty * 8 + i;
                g_H[n * 400 + h] = fmaxf(acc[i][j] + bias, 0.f);
            }
        }
    }
}

// ============================================================================
// Kernel BC: encoder2 + reparam + base
// ============================================================================
__global__ __launch_bounds__(256) void k_enc2_base(const float* __restrict__ w2,
                                                   const float* __restrict__ b2,
                                                   const float* __restrict__ fcw,
                                                   const float* __restrict__ fcb,
                                                   const float* __restrict__ eps) {
    __shared__ float sh[6400];
    __shared__ float shW[1600];
    __shared__ float zs[256];
    const int tid = threadIdx.x;
    const int n0 = blockIdx.x * 16;

#pragma unroll
    for (int ii = 0; ii < 25; ii++) {
        int idx = tid + ii * 256;
        sh[idx] = g_H[n0 * 400 + idx];
    }
    const int nl = tid >> 4, l = tid & 15;
    float mu = 0.f, lv = 0.f;
    for (int ch = 0; ch < 8; ch++) {
        __syncthreads();
        for (int idx = tid; idx < 1600; idx += 256) {
            int row = idx / 50, col = idx % 50;
            shW[idx] = w2[row * 400 + ch * 50 + col];
        }
        __syncthreads();
#pragma unroll
        for (int hh = 0; hh < 50; hh++) {
            float hv = sh[nl * 400 + ch * 50 + hh];
            mu = fmaf(hv, shW[l * 50 + hh], mu);
            lv = fmaf(hv, shW[(16 + l) * 50 + hh], lv);
        }
    }
    mu += b2[l];
    lv += b2[16 + l];
    float z = mu + eps[(n0 + nl) * 16 + l] * __expf(0.5f * lv);
    zs[nl * 16 + l] = z;
    __syncthreads();
#pragma unroll
    for (int ii = 0; ii < 25; ii++) {
        int idx = tid + ii * 256;
        int h = idx >> 4, ll = idx & 15;
        sh[idx] = fcw[h * 32 + ll];
    }
    __syncthreads();
#pragma unroll
    for (int ii = 0; ii < 25; ii++) {
        int idx = tid + ii * 256;
        int nn = idx / 400, h = idx % 400;
        float s = fcb[h];
#pragma unroll
        for (int ll = 0; ll < 16; ll++) s = fmaf(zs[nn * 16 + ll], sh[h * 16 + ll], s);
        g_base[(n0 + nn) * 400 + h] = s;
    }
}

// ============================================================================
// Kernel D: decoder GEMM on mma.sync bf16 + fused BCE.
// grid (32 n-tiles, 16 k), 256 threads (8 warps: 4 n x 2 o), warp = 32n x 56o.
// SMEM: hk bf16 [128][stride 456 halves] + 2 dec_w slab bufs [112][72] + misc.
// ============================================================================
#define HK_WORDS   (128 * 228)              // 116736 B
#define BSLAB_B    16128                    // 112*72*2
#define DEC_SMEM   (116736 + 2 * BSLAB_B + 448 * 4 + 784 * 4 + 128 * 4)

__global__ __launch_bounds__(256) void k_dec_mma(const float* __restrict__ fcw,
                                                 const float* __restrict__ db) {
    extern __shared__ __align__(16) char smem[];
    uint32_t* const hk32 = (uint32_t*)smem;
    const uint32_t* const bw32 = (const uint32_t*)(smem + 116736);
    float* const wxs  = (float*)(smem + 116736 + 2 * BSLAB_B);
    float* const db_s = wxs + 448;
    float* const red  = db_s + 784;
    const uint32_t sbase = smem_u32(smem);
    const uint32_t bB = sbase + 116736;

    const int tid = threadIdx.x, wid = tid >> 5, lane = tid & 31;
    const int wn = wid & 3, wo = wid >> 2;
    const int nt = blockIdx.x, k = blockIdx.y;
    const int n0 = nt * 128;
    const int lr = lane >> 2, lc = lane & 3;

    for (int h = tid; h < 448; h += 256) wxs[h] = (h < 400) ? fcw[h * 32 + 16 + k] : 0.f;
    for (int o = tid; o < 784; o += 256) db_s[o] = db[o];
    if (tid < 128) red[tid] = 0.f;
    __syncthreads();

    // ---- build hk bf16 into smem: hk[n][h] = relu(base[n0+n][h] + wx[h]) ----
    for (int idx = tid; idx < 128 * 200; idx += 256) {
        int n = idx / 200, w = idx % 200;       // w = h-pair index, h = 2w
        const float2 bv = *(const float2*)&g_base[(n0 + n) * 400 + 2 * w];
        float v0 = fmaxf(bv.x + wxs[2 * w], 0.f);
        float v1 = fmaxf(bv.y + wxs[2 * w + 1], 0.f);
        hk32[n * 228 + w] = pack_bf16x2(v0, v1);
    }

    // prefetch slab 0
    {
        const uint4* src = g_dwb;  // (nt-independent) slab 0 of ot 0
        for (int it = tid; it < 1008; it += 256) cp_async16(bB + it * 16, src + it);
        cp_commit();
    }

    float cfr[14][4];
#pragma unroll
    for (int f = 0; f < 14; f++)
#pragma unroll
        for (int j = 0; j < 4; j++) cfr[f][j] = 0.f;
    float acc[2][2] = {{0.f, 0.f}, {0.f, 0.f}};

    const int aRow = wn * 32 + lr;
    int ot = 0, s = 0;
    for (int i = 0; i < 49; i++) {
        const int buf = i & 1;
        cp_wait0();
        __syncthreads();
        if (i < 48) {
            const uint4* src = g_dwb + (i + 1) * 1008;
            const uint32_t dsta = bB + (buf ^ 1) * BSLAB_B;
            for (int it = tid; it < 1008; it += 256) cp_async16(dsta + it * 16, src + it);
            cp_commit();
        }
        // ---- MMA over this slab ----
        const int nks = (s == 6) ? 1 : 4;
        const uint32_t* bslab = bw32 + buf * (BSLAB_B / 4);
        for (int ks = 0; ks < nks; ks++) {
            const int aw = s * 32 + ks * 8 + lc;
            uint32_t a0[4], a1[4];
            {
                int i0 = aRow * 228 + aw;
                a0[0] = hk32[i0];            a0[1] = hk32[i0 + 8 * 228];
                a0[2] = hk32[i0 + 4];        a0[3] = hk32[i0 + 8 * 228 + 4];
                int i1 = i0 + 16 * 228;
                a1[0] = hk32[i1];            a1[1] = hk32[i1 + 8 * 228];
                a1[2] = hk32[i1 + 4];        a1[3] = hk32[i1 + 8 * 228 + 4];
            }
#pragma unroll
            for (int of = 0; of < 7; of++) {
                uint32_t b[2];
                int bi = (wo * 56 + 8 * of + lr) * 36 + ks * 8 + lc;
                b[0] = bslab[bi];
                b[1] = bslab[bi + 4];
                mma16816(cfr[of], a0, b);
                mma16816(cfr[7 + of], a1, b);
            }
        }
        // ---- end of ot: fused BCE epilogue ----
        if (s == 6) {
            const float* yt = g_yt + (nt * 7 + ot) * 14336;
#pragma unroll
            for (int m = 0; m < 2; m++)
#pragma unroll
                for (int of = 0; of < 7; of++)
#pragma unroll
                    for (int j = 0; j < 4; j++) {
                        int o_loc = wo * 56 + 8 * of + lc * 2 + (j & 1);
                        int n_loc = wn * 32 + 16 * m + lr + 8 * (j >> 1);
                        float x = cfr[m * 7 + of][j] + db_s[ot * 112 + o_loc];
                        float ya = __ldg(&yt[o_loc * 128 + n_loc]);
                        float sp = fmaxf(x, 0.f) + __logf(1.f + __expf(-fabsf(x)));
                        acc[m][j >> 1] += ya * fminf(sp - x, 100.f) + (1.f - ya) * fminf(sp, 100.f);
                        cfr[m * 7 + of][j] = 0.f;
                    }
            ot++; s = 0;
        } else {
            s++;
        }
    }
    // reduce row sums: lanes lc 0..3 share rows
#pragma unroll
    for (int m = 0; m < 2; m++)
#pragma unroll
        for (int r = 0; r < 2; r++) {
            float v = acc[m][r];
            v += __shfl_xor_sync(0xffffffffu, v, 1);
            v += __shfl_xor_sync(0xffffffffu, v, 2);
            if (lc == 0) atomicAdd(&red[wn * 32 + 16 * m + 8 * r + lr], v);
        }
    __syncthreads();
    if (tid < 128) g_logb[(n0 + tid) * 16 + k] = -red[tid] * 0.01f;
}

// ============================================================================
// Kernel E: HMM fwd/bwd concurrent (named barriers) + gamma. 32 blocks x 512.
// ============================================================================
__global__ __launch_bounds__(512) void k_hmm(const float* __restrict__ log_pi,
                                             const float* __restrict__ log_A,
                                             float* __restrict__ out) {
    __shared__ float lbs[2048];
    __shared__ float sA[256];
    __shared__ float lp[16];
    __shared__ float as_[2048];
    __shared__ float bs_[2048];
    __shared__ float p0[16], p1[16], q0[16], q1[16];
    const int b = blockIdx.x;
    const int tid = threadIdx.x;
    const unsigned FULL = 0xffffffffu;

#pragma unroll
    for (int ii = 0; ii < 4; ii++) {
        int idx = tid + ii * 512;
        lbs[idx] = g_logb[b * 2048 + idx];
    }
    if (tid < 256) {
        float v = log_A[tid];
        float m = v;
#pragma unroll
        for (int mk = 8; mk >= 1; mk >>= 1) m = fmaxf(m, __shfl_xor_sync(FULL, m, mk));
        float e = __expf(v - m);
        float s = e;
#pragma unroll
        for (int mk = 8; mk >= 1; mk >>= 1) s += __shfl_xor_sync(FULL, s, mk);
        sA[tid] = __logf(e / s + 1e-9f);
    }
    if (tid < 16) {
        float v = log_pi[tid];
        float m = v;
#pragma unroll
        for (int mk = 8; mk >= 1; mk >>= 1) m = fmaxf(m, __shfl_xor_sync(0xffffu, m, mk));
        float e = __expf(v - m);
        float s = e;
#pragma unroll
        for (int mk = 8; mk >= 1; mk >>= 1) s += __shfl_xor_sync(0xffffu, s, mk);
        lp[tid] = __logf(e / s + 1e-9f);
    }
    __syncthreads();
    if (tid < 16) {
        float a = lp[tid] + lbs[tid];
        as_[tid] = a;
        p0[tid] = a;
    }
    if (tid >= 256 && tid < 272) {
        bs_[127 * 16 + (tid - 256)] = 0.f;
        q1[tid - 256] = 0.f;
    }
    __syncthreads();
    if (tid < 256) {
        const int k = tid >> 4, j = tid & 15;
        for (int t = 1; t < 128; t++) {
            const float* src = (t & 1) ? p0 : p1;
            float* dst = (t & 1) ? p1 : p0;
            float v = src[j] + sA[j * 16 + k];
            float m = v;
#pragma unroll
            for (int mk = 8; mk >= 1; mk >>= 1) m = fmaxf(m, __shfl_xor_sync(FULL, m, mk));
            float e = __expf(v - m);
            float s = e;
#pragma unroll
            for (int mk = 8; mk >= 1; mk >>= 1) s += __shfl_xor_sync(FULL, s, mk);
            float cur = m + __logf(s) + lbs[t * 16 + k];
            if (j == 0) { as_[t * 16 + k] = cur; dst[k] = cur; }
            asm volatile("bar.sync 1, 256;" ::: "memory");
        }
    } else {
        const int tid2 = tid - 256;
        const int j = tid2 >> 4, k = tid2 & 15;
        for (int t = 126; t >= 0; t--) {
            const float* src = ((t + 1) & 1) ? q1 : q0;
            float* dst = (t & 1) ? q1 : q0;
            float v = sA[j * 16 + k] + lbs[(t + 1) * 16 + k] + src[k];
            float m = v;
#pragma unroll
            for (int mk = 8; mk >= 1; mk >>= 1) m = fmaxf(m, __shfl_xor_sync(FULL, m, mk));
            float e = __expf(v - m);
            float s = e;
#pragma unroll
            for (int mk = 8; mk >= 1; mk >>= 1) s += __shfl_xor_sync(FULL, s, mk);
            float cur = m + __logf(s);
            if (k == 0) { bs_[t * 16 + j] = cur; dst[j] = cur; }
            asm volatile("bar.sync 2, 256;" ::: "memory");
        }
    }
    __syncthreads();
#pragma unroll
    for (int ii = 0; ii < 4; ii++) {
        int idx = tid + ii * 512;
        g_la[b * 2048 + idx] = as_[idx];
        g_lbeta[b * 2048 + idx] = bs_[idx];
    }
    if (tid < 128) {
        int t = tid;
        float lg[16];
        float m = -1e30f;
#pragma unroll
        for (int kk = 0; kk < 16; kk++) {
            lg[kk] = as_[t * 16 + kk] + bs_[t * 16 + kk];
            m = fmaxf(m, lg[kk]);
        }
        float s = 0.f;
#pragma unroll
        for (int kk = 0; kk < 16; kk++) s += __expf(lg[kk] - m);
        float l = m + __logf(s);
#pragma unroll
        for (int kk = 0; kk < 16; kk++) out[b * 2048 + t * 16 + kk] = __expf(lg[kk] - l);
    }
}

// ============================================================================
// Kernel F: xi
// ============================================================================
__global__ __launch_bounds__(256) void k_xi(const float* __restrict__ log_A,
                                            float* __restrict__ out) {
    __shared__ float sA[256];
    __shared__ float wm[8], ws[8];
    const int t = blockIdx.x;
    const int b = blockIdx.y;
    const int tid = threadIdx.x;
    const int j = tid >> 4, k = tid & 15;
    const unsigned FULL = 0xffffffffu;
    {
        float v = log_A[tid];
        float m = v;
#pragma unroll
        for (int mk = 8; mk >= 1; mk >>= 1) m = fmaxf(m, __shfl_xor_sync(FULL, m, mk));
        float e = __expf(v - m);
        float s = e;
#pragma unroll
        for (int mk = 8; mk >= 1; mk >>= 1) s += __shfl_xor_sync(FULL, s, mk);
        sA[tid] = __logf(e / s + 1e-9f);
    }
    __syncthreads();
    const int nt = b * 128 + t;
    float v = g_la[nt * 16 + j] + sA[tid] + g_logb[(nt + 1) * 16 + k] + g_lbeta[(nt + 1) * 16 + k];
    float m = v;
#pragma unroll
    for (int mk = 16; mk >= 1; mk >>= 1) m = fmaxf(m, __shfl_xor_sync(FULL, m, mk));
    if ((tid & 31) == 0) wm[tid >> 5] = m;
    __syncthreads();
    float M = wm[0];
#pragma unroll
    for (int w = 1; w < 8; w++) M = fmaxf(M, wm[w]);
    float e = __expf(v - M);
    float s = e;
#pragma unroll
    for (int mk = 16; mk >= 1; mk >>= 1) s += __shfl_xor_sync(FULL, s, mk);
    if ((tid & 31) == 0) ws[tid >> 5] = s;
    __syncthreads();
    float S = 0.f;
#pragma unroll
    for (int w = 0; w < 8; w++) S += ws[w];
    out[65536 + (b * 127 + t) * 256 + tid] = __expf(v - M - __logf(S));
}

// ============================================================================
extern "C" void kernel_launch(void* const* d_in, const int* in_sizes, int n_in,
                              void* d_out, int out_size) {
    const float* y   = (const float*)d_in[0];
    const float* w1  = (const float*)d_in[1];
    const float* b1  = (const float*)d_in[2];
    const float* w2  = (const float*)d_in[3];
    const float* b2  = (const float*)d_in[4];
    const float* fcw = (const float*)d_in[5];
    const float* fcb = (const float*)d_in[6];
    const float* dw  = (const float*)d_in[7];
    const float* db  = (const float*)d_in[8];
    const float* lpi = (const float*)d_in[9];
    const float* lA  = (const float*)d_in[10];
    const float* eps = (const float*)d_in[11];
    float* out = (float*)d_out;

    static int attr_done = 0;
    if (!attr_done) {
        cudaFuncSetAttribute(k_dec_mma, cudaFuncAttributeMaxDynamicSharedMemorySize, DEC_SMEM);
        attr_done = 1;
    }

    k_pack_dw<<<(49 * 112 * 72 + 255) / 256, 256>>>(dw);
    k_pack_y<<<dim3(32, 7), 256>>>(y);
    k_enc1<<<dim3(32, 7), 256>>>(y, w1, b1);
    k_enc2_base<<<256, 256>>>(w2, b2, fcw, fcb, eps);
    k_dec_mma<<<dim3(32, 16), 256, DEC_SMEM>>>(fcw, db);
    k_hmm<<<32, 512>>>(lpi, lA, out);
    k_xi<<<dim3(127, 32), 256>>>(lA, out);
}

// round 4
// speedup vs baseline: 3.0759x; 1.0508x over previous
#include <cuda_runtime.h>
#include <cuda_bf16.h>
#include <stdint.h>

// HMM-VAE fused pipeline. enc1 on tf32 mma.sync, decoder on bf16 mma.sync.
// B=32, T=128, N=4096, K=16, L=16, D=784, H=400.

#define N_TOT 4096

// -------- scratch --------
__device__ float g_H[N_TOT * 400];
__device__ float g_base[N_TOT * 400];
__device__ float g_logb[N_TOT * 16];
__device__ float g_la[N_TOT * 16];
__device__ float g_lbeta[N_TOT * 16];
__device__ uint4 g_dwb[49 * 1008];           // dec_w bf16 slabs [ot*7+s][112 o][72 half]
__device__ float g_yt[32 * 7 * 112 * 128];   // y transposed tiles [nt][ot][o][n]

// ======================= helpers =======================
static __device__ __forceinline__ uint32_t smem_u32(const void* p) {
    uint32_t a;
    asm("{ .reg .u64 t; cvta.to.shared.u64 t, %1; cvt.u32.u64 %0, t; }" : "=r"(a) : "l"(p));
    return a;
}
static __device__ __forceinline__ void cp_async16(uint32_t saddr, const void* g) {
    asm volatile("cp.async.cg.shared.global [%0], [%1], 16;" :: "r"(saddr), "l"(g));
}
static __device__ __forceinline__ void cp_commit() {
    asm volatile("cp.async.commit_group;" ::: "memory");
}
static __device__ __forceinline__ void cp_wait0() {
    asm volatile("cp.async.wait_group 0;" ::: "memory");
}
static __device__ __forceinline__ void mma16816(float* c, const uint32_t* a, const uint32_t* b) {
    asm volatile(
        "mma.sync.aligned.m16n8k16.row.col.f32.bf16.bf16.f32 "
        "{%0,%1,%2,%3}, {%4,%5,%6,%7}, {%8,%9}, {%0,%1,%2,%3};"
        : "+f"(c[0]), "+f"(c[1]), "+f"(c[2]), "+f"(c[3])
        : "r"(a[0]), "r"(a[1]), "r"(a[2]), "r"(a[3]), "r"(b[0]), "r"(b[1]));
}
static __device__ __forceinline__ void mma1688_tf32(float* c, const uint32_t* a, const uint32_t* b) {
    asm volatile(
        "mma.sync.aligned.m16n8k8.row.col.f32.tf32.tf32.f32 "
        "{%0,%1,%2,%3}, {%4,%5,%6,%7}, {%8,%9}, {%0,%1,%2,%3};"
        : "+f"(c[0]), "+f"(c[1]), "+f"(c[2]), "+f"(c[3])
        : "r"(a[0]), "r"(a[1]), "r"(a[2]), "r"(a[3]), "r"(b[0]), "r"(b[1]));
}
static __device__ __forceinline__ uint32_t to_tf32(float f) {
    uint32_t r;
    asm("cvt.rna.tf32.f32 %0, %1;" : "=r"(r) : "f"(f));
    return r;
}
static __device__ __forceinline__ uint32_t pack_bf16x2(float a, float b) {
    __nv_bfloat162 t = __floats2bfloat162_rn(a, b);
    return *reinterpret_cast<uint32_t*>(&t);
}

// ============================================================================
// pack kernel: dec_w bf16 slabs + y transpose (merged)
// ============================================================================
#define DW_BLOCKS 1544   // ceil(49*112*72/256)
__global__ __launch_bounds__(256) void k_pack(const float* __restrict__ dw,
                                              const float* __restrict__ y) {
    __shared__ float sm[64 * 113];
    const int bid = blockIdx.x, tid = threadIdx.x;
    if (bid < DW_BLOCKS) {
        int idx = bid * 256 + tid;
        if (idx < 49 * 112 * 72) {
            int slabIdx = idx / 8064, rem = idx % 8064;
            int o = rem / 72, c = rem % 72;
            int ot = slabIdx / 7, s = slabIdx % 7;
            int h = s * 64 + c;
            float v = (c < 64 && h < 400) ? dw[(ot * 112 + o) * 400 + h] : 0.f;
            ((__nv_bfloat16*)g_dwb)[idx] = __float2bfloat16(v);
        }
        return;
    }
    const int b2 = bid - DW_BLOCKS;
    const int nt = b2 / 7, ot = b2 % 7;
    float* outb = g_yt + (nt * 7 + ot) * 14336;
    for (int half = 0; half < 2; half++) {
        int nb = nt * 128 + half * 64;
        for (int idx = tid; idx < 64 * 112; idx += 256) {
            int nl = idx / 112, c = idx % 112;
            sm[nl * 113 + c] = y[(nb + nl) * 784 + ot * 112 + c];
        }
        __syncthreads();
        for (int idx = tid; idx < 112 * 64; idx += 256) {
            int c = idx >> 6, nl = idx & 63;
            outb[c * 128 + half * 64 + nl] = sm[nl * 113 + c];
        }
        __syncthreads();
    }
}

// ============================================================================
// Kernel A: H = relu(Y @ W1^T + b1) on tf32 mma.sync.
// grid (32 n-tiles, 7 h-tiles), 256 threads (8 warps 4n x 2h), warp 32n x 32h.
// K = 784 in 49 chunks of 16, cp.async double-buffered.
// ============================================================================
__global__ __launch_bounds__(256) void k_enc1(const float* __restrict__ y,
                                              const float* __restrict__ w1,
                                              const float* __restrict__ b1) {
    __shared__ __align__(16) float As[2][128 * 20];
    __shared__ __align__(16) float Bs[2][64 * 20];
    const int tid = threadIdx.x, wid = tid >> 5, lane = tid & 31;
    const int wn = wid & 3, wo = wid >> 2;
    const int lr = lane >> 2, lc = lane & 3;
    const int n0 = blockIdx.x * 128;
    const int h0 = blockIdx.y * 64;
    const int vrows = (400 - h0) < 64 ? (400 - h0) : 64;   // valid w1 rows

    const uint32_t aB = smem_u32(As);
    const uint32_t bB = smem_u32(Bs);

    if (vrows < 64) {   // zero invalid rows of both B buffers once
        for (int i = tid; i < 2 * 64 * 20; i += 256) {
            int r = (i % (64 * 20)) / 20;
            if (r >= vrows) ((float*)Bs)[i] = 0.f;
        }
        __syncthreads();
    }

    // prefetch chunk 0
    {
        int r = tid >> 1, seg = tid & 1;   // A: 128 rows x 2 segs of 8 floats? -> use 4-float segs
    }
    // A: 128 rows x 4 segs (16 floats) = 512 cp ops; B: vrows x 4 segs
    {
        int r = tid >> 1;          // unused placeholder (kept simple below)
    }
    auto loadA = [&](int buf, int c0) {
        // 512 cp16: it in [0,512): row = it>>2, seg = it&3
        for (int it = tid; it < 512; it += 256) {
            int row = it >> 2, seg = it & 3;
            cp_async16(aB + (buf * 128 * 20 + row * 20 + seg * 4) * 4,
                       y + (size_t)(n0 + row) * 784 + c0 + seg * 4);
        }
    };
    auto loadB = [&](int buf, int c0) {
        for (int it = tid; it < vrows * 4; it += 256) {
            int row = it >> 2, seg = it & 3;
            cp_async16(bB + (buf * 64 * 20 + row * 20 + seg * 4) * 4,
                       w1 + (size_t)(h0 + row) * 784 + c0 + seg * 4);
        }
    };
    loadA(0, 0); loadB(0, 0); cp_commit();

    float acc[2][4][4];
#pragma unroll
    for (int m = 0; m < 2; m++)
#pragma unroll
        for (int o = 0; o < 4; o++)
#pragma unroll
            for (int j = 0; j < 4; j++) acc[m][o][j] = 0.f;

    for (int ch = 0; ch < 49; ch++) {
        const int buf = ch & 1;
        cp_wait0();
        __syncthreads();
        if (ch < 48) {
            loadA(buf ^ 1, (ch + 1) * 16);
            loadB(buf ^ 1, (ch + 1) * 16);
            cp_commit();
        }
        const float* Ab = As[buf];
        const float* Bb = Bs[buf];
#pragma unroll
        for (int ks = 0; ks < 2; ks++) {
            const int kk = ks * 8;
            uint32_t afr[2][4];
#pragma unroll
            for (int m = 0; m < 2; m++) {
                int r = wn * 32 + m * 16 + lr;
                afr[m][0] = to_tf32(Ab[r * 20 + kk + lc]);
                afr[m][1] = to_tf32(Ab[(r + 8) * 20 + kk + lc]);
                afr[m][2] = to_tf32(Ab[r * 20 + kk + lc + 4]);
                afr[m][3] = to_tf32(Ab[(r + 8) * 20 + kk + lc + 4]);
            }
#pragma unroll
            for (int o = 0; o < 4; o++) {
                int br = wo * 32 + o * 8 + lr;
                uint32_t bfr[2];
                bfr[0] = to_tf32(Bb[br * 20 + kk + lc]);
                bfr[1] = to_tf32(Bb[br * 20 + kk + lc + 4]);
#pragma unroll
                for (int m = 0; m < 2; m++) mma1688_tf32(acc[m][o], afr[m], bfr);
            }
        }
    }
    // epilogue: bias + relu -> g_H
#pragma unroll
    for (int m = 0; m < 2; m++)
#pragma unroll
        for (int o = 0; o < 4; o++)
#pragma unroll
            for (int j = 0; j < 4; j++) {
                int h = h0 + wo * 32 + o * 8 + lc * 2 + (j & 1);
                int n = n0 + wn * 32 + m * 16 + lr + 8 * (j >> 1);
                if (h < 400)
                    g_H[n * 400 + h] = fmaxf(acc[m][o][j] + __ldg(&b1[h]), 0.f);
            }
}

// ============================================================================
// Kernel BC: enc2 (mu/lv GEMM) + z + base GEMM, one kernel.
// grid 64 blocks x 256 threads; block owns 64 n rows.
// ============================================================================
__global__ __launch_bounds__(256) void k_enc2(const float* __restrict__ w2,
                                              const float* __restrict__ b2,
                                              const float* __restrict__ fcw,
                                              const float* __restrict__ fcb,
                                              const float* __restrict__ eps) {
    __shared__ float Asm[64 * 17];
    __shared__ float Bsm[32 * 17];
    __shared__ float zs[64 * 16];
    const int tid = threadIdx.x;
    const int ty = tid >> 4, tx = tid & 15;
    const int n0 = blockIdx.x * 64;

    float amu[4] = {0.f, 0.f, 0.f, 0.f};
    float alv[4] = {0.f, 0.f, 0.f, 0.f};

    for (int ch = 0; ch < 25; ch++) {
        const int k0 = ch * 16;
        for (int i = tid; i < 64 * 16; i += 256) {
            int r = i >> 4, c = i & 15;
            Asm[r * 17 + c] = g_H[(n0 + r) * 400 + k0 + c];
        }
        for (int i = tid; i < 32 * 16; i += 256) {
            int r = i >> 4, c = i & 15;
            Bsm[r * 17 + c] = w2[r * 400 + k0 + c];
        }
        __syncthreads();
#pragma unroll
        for (int c = 0; c < 16; c++) {
            float bmu = Bsm[tx * 17 + c];
            float blv = Bsm[(tx + 16) * 17 + c];
#pragma unroll
            for (int i = 0; i < 4; i++) {
                float a = Asm[(ty * 4 + i) * 17 + c];
                amu[i] = fmaf(a, bmu, amu[i]);
                alv[i] = fmaf(a, blv, alv[i]);
            }
        }
        __syncthreads();
    }
    const float bm = b2[tx], bl = b2[tx + 16];
#pragma unroll
    for (int i = 0; i < 4; i++) {
        int n = ty * 4 + i;
        float mu = amu[i] + bm;
        float lv = alv[i] + bl;
        float z = mu + eps[(n0 + n) * 16 + tx] * __expf(0.5f * lv);
        zs[n * 16 + tx] = z;
    }
    __syncthreads();
    // base: thread owns h = tid (+256); Wz rows in registers, z broadcast from smem
    float w0[16], w1r[16], fb0 = 0.f, fb1 = 0.f;
    const int h0i = tid, h1i = tid + 256;
    {
        const float4* p = (const float4*)&fcw[h0i * 32];
#pragma unroll
        for (int q = 0; q < 4; q++) {
            float4 v = p[q];
            w0[q * 4 + 0] = v.x; w0[q * 4 + 1] = v.y; w0[q * 4 + 2] = v.z; w0[q * 4 + 3] = v.w;
        }
        fb0 = fcb[h0i];
    }
    if (h1i < 400) {
        const float4* p = (const float4*)&fcw[h1i * 32];
#pragma unroll
        for (int q = 0; q < 4; q++) {
            float4 v = p[q];
            w1r[q * 4 + 0] = v.x; w1r[q * 4 + 1] = v.y; w1r[q * 4 + 2] = v.z; w1r[q * 4 + 3] = v.w;
        }
        fb1 = fcb[h1i];
    }
    for (int n = 0; n < 64; n++) {
        float zr[16];
#pragma unroll
        for (int l = 0; l < 16; l++) zr[l] = zs[n * 16 + l];
        float s0 = fb0, s1 = fb1;
#pragma unroll
        for (int l = 0; l < 16; l++) {
            s0 = fmaf(zr[l], w0[l], s0);
            if (h1i < 400) s1 = fmaf(zr[l], w1r[l], s1);
        }
        g_base[(n0 + n) * 400 + h0i] = s0;
        if (h1i < 400) g_base[(n0 + n) * 400 + h1i] = s1;
    }
}

// ============================================================================
// Kernel D: decoder GEMM on mma.sync bf16 + fused BCE. (unchanged from R3)
// ============================================================================
#define BSLAB_B    16128
#define DEC_SMEM   (116736 + 2 * BSLAB_B + 448 * 4 + 784 * 4 + 128 * 4)

__global__ __launch_bounds__(256) void k_dec_mma(const float* __restrict__ fcw,
                                                 const float* __restrict__ db) {
    extern __shared__ __align__(16) char smem[];
    uint32_t* const hk32 = (uint32_t*)smem;
    const uint32_t* const bw32 = (const uint32_t*)(smem + 116736);
    float* const wxs  = (float*)(smem + 116736 + 2 * BSLAB_B);
    float* const db_s = wxs + 448;
    float* const red  = db_s + 784;
    const uint32_t bB = smem_u32(smem) + 116736;

    const int tid = threadIdx.x, wid = tid >> 5, lane = tid & 31;
    const int wn = wid & 3, wo = wid >> 2;
    const int nt = blockIdx.x, k = blockIdx.y;
    const int n0 = nt * 128;
    const int lr = lane >> 2, lc = lane & 3;

    for (int h = tid; h < 448; h += 256) wxs[h] = (h < 400) ? fcw[h * 32 + 16 + k] : 0.f;
    for (int o = tid; o < 784; o += 256) db_s[o] = db[o];
    if (tid < 128) red[tid] = 0.f;
    __syncthreads();

    for (int idx = tid; idx < 128 * 200; idx += 256) {
        int n = idx / 200, w = idx % 200;
        const float2 bv = *(const float2*)&g_base[(n0 + n) * 400 + 2 * w];
        float v0 = fmaxf(bv.x + wxs[2 * w], 0.f);
        float v1 = fmaxf(bv.y + wxs[2 * w + 1], 0.f);
        hk32[n * 228 + w] = pack_bf16x2(v0, v1);
    }

    {
        const uint4* src = g_dwb;
        for (int it = tid; it < 1008; it += 256) cp_async16(bB + it * 16, src + it);
        cp_commit();
    }

    float cfr[14][4];
#pragma unroll
    for (int f = 0; f < 14; f++)
#pragma unroll
        for (int j = 0; j < 4; j++) cfr[f][j] = 0.f;
    float acc[2][2] = {{0.f, 0.f}, {0.f, 0.f}};

    const int aRow = wn * 32 + lr;
    int ot = 0, s = 0;
    for (int i = 0; i < 49; i++) {
        const int buf = i & 1;
        cp_wait0();
        __syncthreads();
        if (i < 48) {
            const uint4* src = g_dwb + (i + 1) * 1008;
            const uint32_t dsta = bB + (buf ^ 1) * BSLAB_B;
            for (int it = tid; it < 1008; it += 256) cp_async16(dsta + it * 16, src + it);
            cp_commit();
        }
        const int nks = (s == 6) ? 1 : 4;
        const uint32_t* bslab = bw32 + buf * (BSLAB_B / 4);
        for (int ks = 0; ks < nks; ks++) {
            const int aw = s * 32 + ks * 8 + lc;
            uint32_t a0[4], a1[4];
            {
                int i0 = aRow * 228 + aw;
                a0[0] = hk32[i0];            a0[1] = hk32[i0 + 8 * 228];
                a0[2] = hk32[i0 + 4];        a0[3] = hk32[i0 + 8 * 228 + 4];
                int i1 = i0 + 16 * 228;
                a1[0] = hk32[i1];            a1[1] = hk32[i1 + 8 * 228];
                a1[2] = hk32[i1 + 4];        a1[3] = hk32[i1 + 8 * 228 + 4];
            }
#pragma unroll
            for (int of = 0; of < 7; of++) {
                uint32_t b[2];
                int bi = (wo * 56 + 8 * of + lr) * 36 + ks * 8 + lc;
                b[0] = bslab[bi];
                b[1] = bslab[bi + 4];
                mma16816(cfr[of], a0, b);
                mma16816(cfr[7 + of], a1, b);
            }
        }
        if (s == 6) {
            const float* yt = g_yt + (nt * 7 + ot) * 14336;
#pragma unroll
            for (int m = 0; m < 2; m++)
#pragma unroll
                for (int of = 0; of < 7; of++)
#pragma unroll
                    for (int j = 0; j < 4; j++) {
                        int o_loc = wo * 56 + 8 * of + lc * 2 + (j & 1);
                        int n_loc = wn * 32 + 16 * m + lr + 8 * (j >> 1);
                        float x = cfr[m * 7 + of][j] + db_s[ot * 112 + o_loc];
                        float ya = __ldg(&yt[o_loc * 128 + n_loc]);
                        float sp = fmaxf(x, 0.f) + __logf(1.f + __expf(-fabsf(x)));
                        acc[m][j >> 1] += ya * fminf(sp - x, 100.f) + (1.f - ya) * fminf(sp, 100.f);
                        cfr[m * 7 + of][j] = 0.f;
                    }
            ot++; s = 0;
        } else {
            s++;
        }
    }
#pragma unroll
    for (int m = 0; m < 2; m++)
#pragma unroll
        for (int r = 0; r < 2; r++) {
            float v = acc[m][r];
            v += __shfl_xor_sync(0xffffffffu, v, 1);
            v += __shfl_xor_sync(0xffffffffu, v, 2);
            if (lc == 0) atomicAdd(&red[wn * 32 + 16 * m + 8 * r + lr], v);
        }
    __syncthreads();
    if (tid < 128) g_logb[(n0 + tid) * 16 + k] = -red[tid] * 0.01f;
}

// ============================================================================
// Kernel E: HMM fwd/bwd concurrent + gamma. (unchanged from R3)
// ============================================================================
__global__ __launch_bounds__(512) void k_hmm(const float* __restrict__ log_pi,
                                             const float* __restrict__ log_A,
                                             float* __restrict__ out) {
    __shared__ float lbs[2048];
    __shared__ float sA[256];
    __shared__ float lp[16];
    __shared__ float as_[2048];
    __shared__ float bs_[2048];
    __shared__ float p0[16], p1[16], q0[16], q1[16];
    const int b = blockIdx.x;
    const int tid = threadIdx.x;
    const unsigned FULL = 0xffffffffu;

#pragma unroll
    for (int ii = 0; ii < 4; ii++) {
        int idx = tid + ii * 512;
        lbs[idx] = g_logb[b * 2048 + idx];
    }
    if (tid < 256) {
        float v = log_A[tid];
        float m = v;
#pragma unroll
        for (int mk = 8; mk >= 1; mk >>= 1) m = fmaxf(m, __shfl_xor_sync(FULL, m, mk));
        float e = __expf(v - m);
        float s = e;
#pragma unroll
        for (int mk = 8; mk >= 1; mk >>= 1) s += __shfl_xor_sync(FULL, s, mk);
        sA[tid] = __logf(e / s + 1e-9f);
    }
    if (tid < 16) {
        float v = log_pi[tid];
        float m = v;
#pragma unroll
        for (int mk = 8; mk >= 1; mk >>= 1) m = fmaxf(m, __shfl_xor_sync(0xffffu, m, mk));
        float e = __expf(v - m);
        float s = e;
#pragma unroll
        for (int mk = 8; mk >= 1; mk >>= 1) s += __shfl_xor_sync(0xffffu, s, mk);
        lp[tid] = __logf(e / s + 1e-9f);
    }
    __syncthreads();
    if (tid < 16) {
        float a = lp[tid] + lbs[tid];
        as_[tid] = a;
        p0[tid] = a;
    }
    if (tid >= 256 && tid < 272) {
        bs_[127 * 16 + (tid - 256)] = 0.f;
        q1[tid - 256] = 0.f;
    }
    __syncthreads();
    if (tid < 256) {
        const int k = tid >> 4, j = tid & 15;
        for (int t = 1; t < 128; t++) {
            const float* src = (t & 1) ? p0 : p1;
            float* dst = (t & 1) ? p1 : p0;
            float v = src[j] + sA[j * 16 + k];
            float m = v;
#pragma unroll
            for (int mk = 8; mk >= 1; mk >>= 1) m = fmaxf(m, __shfl_xor_sync(FULL, m, mk));
            float e = __expf(v - m);
            float s = e;
#pragma unroll
            for (int mk = 8; mk >= 1; mk >>= 1) s += __shfl_xor_sync(FULL, s, mk);
            float cur = m + __logf(s) + lbs[t * 16 + k];
            if (j == 0) { as_[t * 16 + k] = cur; dst[k] = cur; }
            asm volatile("bar.sync 1, 256;" ::: "memory");
        }
    } else {
        const int tid2 = tid - 256;
        const int j = tid2 >> 4, k = tid2 & 15;
        for (int t = 126; t >= 0; t--) {
            const float* src = ((t + 1) & 1) ? q1 : q0;
            float* dst = (t & 1) ? q1 : q0;
            float v = sA[j * 16 + k] + lbs[(t + 1) * 16 + k] + src[k];
            float m = v;
#pragma unroll
            for (int mk = 8; mk >= 1; mk >>= 1) m = fmaxf(m, __shfl_xor_sync(FULL, m, mk));
            float e = __expf(v - m);
            float s = e;
#pragma unroll
            for (int mk = 8; mk >= 1; mk >>= 1) s += __shfl_xor_sync(FULL, s, mk);
            float cur = m + __logf(s);
            if (k == 0) { bs_[t * 16 + j] = cur; dst[j] = cur; }
            asm volatile("bar.sync 2, 256;" ::: "memory");
        }
    }
    __syncthreads();
#pragma unroll
    for (int ii = 0; ii < 4; ii++) {
        int idx = tid + ii * 512;
        g_la[b * 2048 + idx] = as_[idx];
        g_lbeta[b * 2048 + idx] = bs_[idx];
    }
    if (tid < 128) {
        int t = tid;
        float lg[16];
        float m = -1e30f;
#pragma unroll
        for (int kk = 0; kk < 16; kk++) {
            lg[kk] = as_[t * 16 + kk] + bs_[t * 16 + kk];
            m = fmaxf(m, lg[kk]);
        }
        float s = 0.f;
#pragma unroll
        for (int kk = 0; kk < 16; kk++) s += __expf(lg[kk] - m);
        float l = m + __logf(s);
#pragma unroll
        for (int kk = 0; kk < 16; kk++) out[b * 2048 + t * 16 + kk] = __expf(lg[kk] - l);
    }
}

// ============================================================================
// Kernel F: xi. grid (16, 32), block 256; each block does 8 t values.
// ============================================================================
__global__ __launch_bounds__(256) void k_xi(const float* __restrict__ log_A,
                                            float* __restrict__ out) {
    __shared__ float sA[256];
    __shared__ float wm[8], ws[8];
    const int b = blockIdx.y;
    const int tid = threadIdx.x;
    const int j = tid >> 4, k = tid & 15;
    const unsigned FULL = 0xffffffffu;
    {
        float v = log_A[tid];
        float m = v;
#pragma unroll
        for (int mk = 8; mk >= 1; mk >>= 1) m = fmaxf(m, __shfl_xor_sync(FULL, m, mk));
        float e = __expf(v - m);
        float s = e;
#pragma unroll
        for (int mk = 8; mk >= 1; mk >>= 1) s += __shfl_xor_sync(FULL, s, mk);
        sA[tid] = __logf(e / s + 1e-9f);
    }
    __syncthreads();
    const float sAv = sA[tid];
    for (int tt = 0; tt < 8; tt++) {
        const int t = blockIdx.x * 8 + tt;
        if (t >= 127) break;
        const int nt = b * 128 + t;
        float v = g_la[nt * 16 + j] + sAv + g_logb[(nt + 1) * 16 + k] + g_lbeta[(nt + 1) * 16 + k];
        float m = v;
#pragma unroll
        for (int mk = 16; mk >= 1; mk >>= 1) m = fmaxf(m, __shfl_xor_sync(FULL, m, mk));
        if ((tid & 31) == 0) wm[tid >> 5] = m;
        __syncthreads();
        float M = wm[0];
#pragma unroll
        for (int w = 1; w < 8; w++) M = fmaxf(M, wm[w]);
        float e = __expf(v - M);
        float s = e;
#pragma unroll
        for (int mk = 16; mk >= 1; mk >>= 1) s += __shfl_xor_sync(FULL, s, mk);
        if ((tid & 31) == 0) ws[tid >> 5] = s;
        __syncthreads();
        float S = 0.f;
#pragma unroll
        for (int w = 0; w < 8; w++) S += ws[w];
        out[65536 + (b * 127 + t) * 256 + tid] = __expf(v - M - __logf(S));
        __syncthreads();
    }
}

// ============================================================================
extern "C" void kernel_launch(void* const* d_in, const int* in_sizes, int n_in,
                              void* d_out, int out_size) {
    const float* y   = (const float*)d_in[0];
    const float* w1  = (const float*)d_in[1];
    const float* b1  = (const float*)d_in[2];
    const float* w2  = (const float*)d_in[3];
    const float* b2  = (const float*)d_in[4];
    const float* fcw = (const float*)d_in[5];
    const float* fcb = (const float*)d_in[6];
    const float* dw  = (const float*)d_in[7];
    const float* db  = (const float*)d_in[8];
    const float* lpi = (const float*)d_in[9];
    const float* lA  = (const float*)d_in[10];
    const float* eps = (const float*)d_in[11];
    float* out = (float*)d_out;

    static int attr_done = 0;
    if (!attr_done) {
        cudaFuncSetAttribute(k_dec_mma, cudaFuncAttributeMaxDynamicSharedMemorySize, DEC_SMEM);
        attr_done = 1;
    }

    k_pack<<<DW_BLOCKS + 224, 256>>>(dw, y);
    k_enc1<<<dim3(32, 7), 256>>>(y, w1, b1);
    k_enc2<<<64, 256>>>(w2, b2, fcw, fcb, eps);
    k_dec_mma<<<dim3(32, 16), 256, DEC_SMEM>>>(fcw, db);
    k_hmm<<<32, 512>>>(lpi, lA, out);
    k_xi<<<dim3(16, 32), 256>>>(lA, out);
}

// round 5
// speedup vs baseline: 3.2225x; 1.0477x over previous
#include <cuda_runtime.h>
#include <cuda_bf16.h>
#include <stdint.h>

// HMM-VAE fused pipeline. enc1 on tf32 mma.sync, decoder on bf16 mma.sync
// with ldmatrix operand loads + depth-2 cp.async pipeline.
// B=32, T=128, N=4096, K=16, L=16, D=784, H=400.

#define N_TOT 4096

// -------- scratch --------
__device__ float g_H[N_TOT * 400];
__device__ float g_base[N_TOT * 400];
__device__ float g_logb[N_TOT * 16];
__device__ float g_la[N_TOT * 16];
__device__ float g_lbeta[N_TOT * 16];
__device__ uint4 g_dwb[49 * 1008];           // dec_w bf16 slabs [ot*7+s][112 o][72 half]
__device__ float g_yt[32 * 7 * 112 * 128];   // y transposed tiles [nt][ot][o][n]

// ======================= helpers =======================
static __device__ __forceinline__ uint32_t smem_u32(const void* p) {
    uint32_t a;
    asm("{ .reg .u64 t; cvta.to.shared.u64 t, %1; cvt.u32.u64 %0, t; }" : "=r"(a) : "l"(p));
    return a;
}
static __device__ __forceinline__ void cp_async16(uint32_t saddr, const void* g) {
    asm volatile("cp.async.cg.shared.global [%0], [%1], 16;" :: "r"(saddr), "l"(g));
}
static __device__ __forceinline__ void cp_commit() {
    asm volatile("cp.async.commit_group;" ::: "memory");
}
static __device__ __forceinline__ void cp_wait0() {
    asm volatile("cp.async.wait_group 0;" ::: "memory");
}
static __device__ __forceinline__ void cp_wait1() {
    asm volatile("cp.async.wait_group 1;" ::: "memory");
}
static __device__ __forceinline__ void ldsm_x4(uint32_t& r0, uint32_t& r1, uint32_t& r2,
                                               uint32_t& r3, uint32_t addr) {
    asm volatile("ldmatrix.sync.aligned.m8n8.x4.shared.b16 {%0,%1,%2,%3}, [%4];"
                 : "=r"(r0), "=r"(r1), "=r"(r2), "=r"(r3) : "r"(addr));
}
static __device__ __forceinline__ void ldsm_x2(uint32_t& r0, uint32_t& r1, uint32_t addr) {
    asm volatile("ldmatrix.sync.aligned.m8n8.x2.shared.b16 {%0,%1}, [%2];"
                 : "=r"(r0), "=r"(r1) : "r"(addr));
}
static __device__ __forceinline__ void mma16816(float* c, const uint32_t* a, const uint32_t* b) {
    asm volatile(
        "mma.sync.aligned.m16n8k16.row.col.f32.bf16.bf16.f32 "
        "{%0,%1,%2,%3}, {%4,%5,%6,%7}, {%8,%9}, {%0,%1,%2,%3};"
        : "+f"(c[0]), "+f"(c[1]), "+f"(c[2]), "+f"(c[3])
        : "r"(a[0]), "r"(a[1]), "r"(a[2]), "r"(a[3]), "r"(b[0]), "r"(b[1]));
}
static __device__ __forceinline__ void mma1688_tf32(float* c, const uint32_t* a, const uint32_t* b) {
    asm volatile(
        "mma.sync.aligned.m16n8k8.row.col.f32.tf32.tf32.f32 "
        "{%0,%1,%2,%3}, {%4,%5,%6,%7}, {%8,%9}, {%0,%1,%2,%3};"
        : "+f"(c[0]), "+f"(c[1]), "+f"(c[2]), "+f"(c[3])
        : "r"(a[0]), "r"(a[1]), "r"(a[2]), "r"(a[3]), "r"(b[0]), "r"(b[1]));
}
static __device__ __forceinline__ uint32_t to_tf32(float f) {
    uint32_t r;
    asm("cvt.rna.tf32.f32 %0, %1;" : "=r"(r) : "f"(f));
    return r;
}
static __device__ __forceinline__ uint32_t pack_bf16x2(float a, float b) {
    __nv_bfloat162 t = __floats2bfloat162_rn(a, b);
    return *reinterpret_cast<uint32_t*>(&t);
}

// ============================================================================
// pack kernel: dec_w bf16 slabs + y transpose (merged)
// ============================================================================
#define DW_BLOCKS 1544   // ceil(49*112*72/256)
__global__ __launch_bounds__(256) void k_pack(const float* __restrict__ dw,
                                              const float* __restrict__ y) {
    __shared__ float sm[64 * 113];
    const int bid = blockIdx.x, tid = threadIdx.x;
    if (bid < DW_BLOCKS) {
        int idx = bid * 256 + tid;
        if (idx < 49 * 112 * 72) {
            int slabIdx = idx / 8064, rem = idx % 8064;
            int o = rem / 72, c = rem % 72;
            int ot = slabIdx / 7, s = slabIdx % 7;
            int h = s * 64 + c;
            float v = (c < 64 && h < 400) ? dw[(ot * 112 + o) * 400 + h] : 0.f;
            ((__nv_bfloat16*)g_dwb)[idx] = __float2bfloat16(v);
        }
        return;
    }
    const int b2 = bid - DW_BLOCKS;
    const int nt = b2 / 7, ot = b2 % 7;
    float* outb = g_yt + (nt * 7 + ot) * 14336;
    for (int half = 0; half < 2; half++) {
        int nb = nt * 128 + half * 64;
        for (int idx = tid; idx < 64 * 112; idx += 256) {
            int nl = idx / 112, c = idx % 112;
            sm[nl * 113 + c] = y[(nb + nl) * 784 + ot * 112 + c];
        }
        __syncthreads();
        for (int idx = tid; idx < 112 * 64; idx += 256) {
            int c = idx >> 6, nl = idx & 63;
            outb[c * 128 + half * 64 + nl] = sm[nl * 113 + c];
        }
        __syncthreads();
    }
}

// ============================================================================
// Kernel A: H = relu(Y @ W1^T + b1) on tf32 mma.sync.
// ============================================================================
__global__ __launch_bounds__(256) void k_enc1(const float* __restrict__ y,
                                              const float* __restrict__ w1,
                                              const float* __restrict__ b1) {
    __shared__ __align__(16) float As[2][128 * 20];
    __shared__ __align__(16) float Bs[2][64 * 20];
    const int tid = threadIdx.x, wid = tid >> 5, lane = tid & 31;
    const int wn = wid & 3, wo = wid >> 2;
    const int lr = lane >> 2, lc = lane & 3;
    const int n0 = blockIdx.x * 128;
    const int h0 = blockIdx.y * 64;
    const int vrows = (400 - h0) < 64 ? (400 - h0) : 64;

    const uint32_t aB = smem_u32(As);
    const uint32_t bB = smem_u32(Bs);

    if (vrows < 64) {
        for (int i = tid; i < 2 * 64 * 20; i += 256) {
            int r = (i % (64 * 20)) / 20;
            if (r >= vrows) ((float*)Bs)[i] = 0.f;
        }
        __syncthreads();
    }

    auto loadA = [&](int buf, int c0) {
        for (int it = tid; it < 512; it += 256) {
            int row = it >> 2, seg = it & 3;
            cp_async16(aB + (buf * 128 * 20 + row * 20 + seg * 4) * 4,
                       y + (size_t)(n0 + row) * 784 + c0 + seg * 4);
        }
    };
    auto loadB = [&](int buf, int c0) {
        for (int it = tid; it < vrows * 4; it += 256) {
            int row = it >> 2, seg = it & 3;
            cp_async16(bB + (buf * 64 * 20 + row * 20 + seg * 4) * 4,
                       w1 + (size_t)(h0 + row) * 784 + c0 + seg * 4);
        }
    };
    loadA(0, 0); loadB(0, 0); cp_commit();

    float acc[2][4][4];
#pragma unroll
    for (int m = 0; m < 2; m++)
#pragma unroll
        for (int o = 0; o < 4; o++)
#pragma unroll
            for (int j = 0; j < 4; j++) acc[m][o][j] = 0.f;

    for (int ch = 0; ch < 49; ch++) {
        const int buf = ch & 1;
        cp_wait0();
        __syncthreads();
        if (ch < 48) {
            loadA(buf ^ 1, (ch + 1) * 16);
            loadB(buf ^ 1, (ch + 1) * 16);
            cp_commit();
        }
        const float* Ab = As[buf];
        const float* Bb = Bs[buf];
#pragma unroll
        for (int ks = 0; ks < 2; ks++) {
            const int kk = ks * 8;
            uint32_t afr[2][4];
#pragma unroll
            for (int m = 0; m < 2; m++) {
                int r = wn * 32 + m * 16 + lr;
                afr[m][0] = to_tf32(Ab[r * 20 + kk + lc]);
                afr[m][1] = to_tf32(Ab[(r + 8) * 20 + kk + lc]);
                afr[m][2] = to_tf32(Ab[r * 20 + kk + lc + 4]);
                afr[m][3] = to_tf32(Ab[(r + 8) * 20 + kk + lc + 4]);
            }
#pragma unroll
            for (int o = 0; o < 4; o++) {
                int br = wo * 32 + o * 8 + lr;
                uint32_t bfr[2];
                bfr[0] = to_tf32(Bb[br * 20 + kk + lc]);
                bfr[1] = to_tf32(Bb[br * 20 + kk + lc + 4]);
#pragma unroll
                for (int m = 0; m < 2; m++) mma1688_tf32(acc[m][o], afr[m], bfr);
            }
        }
    }
#pragma unroll
    for (int m = 0; m < 2; m++)
#pragma unroll
        for (int o = 0; o < 4; o++)
#pragma unroll
            for (int j = 0; j < 4; j++) {
                int h = h0 + wo * 32 + o * 8 + lc * 2 + (j & 1);
                int n = n0 + wn * 32 + m * 16 + lr + 8 * (j >> 1);
                if (h < 400)
                    g_H[n * 400 + h] = fmaxf(acc[m][o][j] + __ldg(&b1[h]), 0.f);
            }
}

// ============================================================================
// Kernel BC: enc2 (mu/lv GEMM) + z + base GEMM
// ============================================================================
__global__ __launch_bounds__(256) void k_enc2(const float* __restrict__ w2,
                                              const float* __restrict__ b2,
                                              const float* __restrict__ fcw,
                                              const float* __restrict__ fcb,
                                              const float* __restrict__ eps) {
    __shared__ float Asm[64 * 17];
    __shared__ float Bsm[32 * 17];
    __shared__ float zs[64 * 16];
    const int tid = threadIdx.x;
    const int ty = tid >> 4, tx = tid & 15;
    const int n0 = blockIdx.x * 64;

    float amu[4] = {0.f, 0.f, 0.f, 0.f};
    float alv[4] = {0.f, 0.f, 0.f, 0.f};

    for (int ch = 0; ch < 25; ch++) {
        const int k0 = ch * 16;
        for (int i = tid; i < 64 * 16; i += 256) {
            int r = i >> 4, c = i & 15;
            Asm[r * 17 + c] = g_H[(n0 + r) * 400 + k0 + c];
        }
        for (int i = tid; i < 32 * 16; i += 256) {
            int r = i >> 4, c = i & 15;
            Bsm[r * 17 + c] = w2[r * 400 + k0 + c];
        }
        __syncthreads();
#pragma unroll
        for (int c = 0; c < 16; c++) {
            float bmu = Bsm[tx * 17 + c];
            float blv = Bsm[(tx + 16) * 17 + c];
#pragma unroll
            for (int i = 0; i < 4; i++) {
                float a = Asm[(ty * 4 + i) * 17 + c];
                amu[i] = fmaf(a, bmu, amu[i]);
                alv[i] = fmaf(a, blv, alv[i]);
            }
        }
        __syncthreads();
    }
    const float bm = b2[tx], bl = b2[tx + 16];
#pragma unroll
    for (int i = 0; i < 4; i++) {
        int n = ty * 4 + i;
        float mu = amu[i] + bm;
        float lv = alv[i] + bl;
        float z = mu + eps[(n0 + n) * 16 + tx] * __expf(0.5f * lv);
        zs[n * 16 + tx] = z;
    }
    __syncthreads();
    float w0[16], w1r[16], fb0 = 0.f, fb1 = 0.f;
    const int h0i = tid, h1i = tid + 256;
    {
        const float4* p = (const float4*)&fcw[h0i * 32];
#pragma unroll
        for (int q = 0; q < 4; q++) {
            float4 v = p[q];
            w0[q * 4 + 0] = v.x; w0[q * 4 + 1] = v.y; w0[q * 4 + 2] = v.z; w0[q * 4 + 3] = v.w;
        }
        fb0 = fcb[h0i];
    }
    if (h1i < 400) {
        const float4* p = (const float4*)&fcw[h1i * 32];
#pragma unroll
        for (int q = 0; q < 4; q++) {
            float4 v = p[q];
            w1r[q * 4 + 0] = v.x; w1r[q * 4 + 1] = v.y; w1r[q * 4 + 2] = v.z; w1r[q * 4 + 3] = v.w;
        }
        fb1 = fcb[h1i];
    }
    for (int n = 0; n < 64; n++) {
        float zr[16];
#pragma unroll
        for (int l = 0; l < 16; l++) zr[l] = zs[n * 16 + l];
        float s0 = fb0, s1 = fb1;
#pragma unroll
        for (int l = 0; l < 16; l++) {
            s0 = fmaf(zr[l], w0[l], s0);
            if (h1i < 400) s1 = fmaf(zr[l], w1r[l], s1);
        }
        g_base[(n0 + n) * 400 + h0i] = s0;
        if (h1i < 400) g_base[(n0 + n) * 400 + h1i] = s1;
    }
}

// ============================================================================
// Kernel D: decoder GEMM (bf16 mma.sync + ldmatrix) + fused BCE.
// grid (32, 16), 256 threads; hk bf16 [128][456h] + 3 dec_w slab bufs [112][72h].
// ============================================================================
#define BSLAB_B    16128
#define HK_BYTES   116736
#define DEC_SMEM   (HK_BYTES + 3 * BSLAB_B + 448 * 4 + 784 * 4 + 128 * 4)

__global__ __launch_bounds__(256) void k_dec_mma(const float* __restrict__ fcw,
                                                 const float* __restrict__ db) {
    extern __shared__ __align__(16) char smem[];
    uint32_t* const hk32 = (uint32_t*)smem;
    float* const wxs  = (float*)(smem + HK_BYTES + 3 * BSLAB_B);
    float* const db_s = wxs + 448;
    float* const red  = db_s + 784;
    const uint32_t hkB = smem_u32(smem);
    const uint32_t bB = hkB + HK_BYTES;

    const int tid = threadIdx.x, wid = tid >> 5, lane = tid & 31;
    const int wn = wid & 3, wo = wid >> 2;
    const int nt = blockIdx.x, k = blockIdx.y;
    const int n0 = nt * 128;
    const int lr = lane >> 2, lc = lane & 3;

    for (int h = tid; h < 448; h += 256) wxs[h] = (h < 400) ? fcw[h * 32 + 16 + k] : 0.f;
    for (int o = tid; o < 784; o += 256) db_s[o] = db[o];
    if (tid < 128) red[tid] = 0.f;
    __syncthreads();

    // ---- build hk bf16: hk[n][h] = relu(base[n0+n][h] + wx[h]) ----
    for (int idx = tid; idx < 128 * 200; idx += 256) {
        int n = idx / 200, w = idx % 200;
        const float2 bv = *(const float2*)&g_base[(n0 + n) * 400 + 2 * w];
        float v0 = fmaxf(bv.x + wxs[2 * w], 0.f);
        float v1 = fmaxf(bv.y + wxs[2 * w + 1], 0.f);
        hk32[n * 228 + w] = pack_bf16x2(v0, v1);
    }

    // prefetch slabs 0 and 1 (separate commit groups)
    for (int it = tid; it < 1008; it += 256) cp_async16(bB + it * 16, g_dwb + it);
    cp_commit();
    for (int it = tid; it < 1008; it += 256) cp_async16(bB + BSLAB_B + it * 16, g_dwb + 1008 + it);
    cp_commit();

    // ---- per-lane ldmatrix base addresses ----
    // A: rows = wn*32 + (lane&15), k-col byte = ((lane>>4)*8)*2
    const uint32_t aBase = hkB + (uint32_t)(wn * 32 + (lane & 15)) * 912 + ((lane >> 4) << 4);
    // B: row = wo*56 + (lane&7) + ((lane>>4)&1)*8 ... via quad q = lane>>3:
    const int bq = lane >> 3;
    const uint32_t bLane = (uint32_t)(wo * 56 + (lane & 7) + (bq >> 1) * 8) * 144 + (bq & 1) * 16;

    float cfr[14][4];
#pragma unroll
    for (int f = 0; f < 14; f++)
#pragma unroll
        for (int j = 0; j < 4; j++) cfr[f][j] = 0.f;
    float acc[2][2] = {{0.f, 0.f}, {0.f, 0.f}};

    int ot = 0, s = 0;
    for (int i = 0; i < 49; i++) {
        if (i < 48) cp_wait1(); else cp_wait0();
        __syncthreads();
        if (i + 2 < 49) {
            const uint4* src = g_dwb + (i + 2) * 1008;
            const uint32_t dsta = bB + ((i + 2) % 3) * BSLAB_B;
            for (int it = tid; it < 1008; it += 256) cp_async16(dsta + it * 16, src + it);
            cp_commit();
        }
        // ---- MMA over slab i (buf i%3) ----
        const int nks = (s == 6) ? 1 : 4;
        const uint32_t aS = aBase + s * 128;
        const uint32_t bS = bB + (i % 3) * BSLAB_B + bLane;
        for (int ks = 0; ks < nks; ks++) {
            const uint32_t aAddr = aS + ks * 32;
            const uint32_t bAddr = bS + ks * 32;
            uint32_t A0[4], A1[4];
            ldsm_x4(A0[0], A0[1], A0[2], A0[3], aAddr);
            ldsm_x4(A1[0], A1[1], A1[2], A1[3], aAddr + 14592);
#pragma unroll
            for (int p = 0; p < 3; p++) {
                uint32_t b0, b1, b2, b3;
                ldsm_x4(b0, b1, b2, b3, bAddr + p * 2304);
                uint32_t bb0[2] = {b0, b1};
                uint32_t bb1[2] = {b2, b3};
                mma16816(cfr[2 * p], A0, bb0);
                mma16816(cfr[7 + 2 * p], A1, bb0);
                mma16816(cfr[2 * p + 1], A0, bb1);
                mma16816(cfr[7 + 2 * p + 1], A1, bb1);
            }
            {
                uint32_t b0, b1;
                ldsm_x2(b0, b1, bAddr + 3 * 2304);
                uint32_t bb[2] = {b0, b1};
                mma16816(cfr[6], A0, bb);
                mma16816(cfr[13], A1, bb);
            }
        }
        // ---- end of ot: fused BCE epilogue ----
        if (s == 6) {
            const float* yt = g_yt + (nt * 7 + ot) * 14336;
#pragma unroll
            for (int m = 0; m < 2; m++)
#pragma unroll
                for (int of = 0; of < 7; of++)
#pragma unroll
                    for (int j = 0; j < 4; j++) {
                        int o_loc = wo * 56 + 8 * of + lc * 2 + (j & 1);
                        int n_loc = wn * 32 + 16 * m + lr + 8 * (j >> 1);
                        float x = cfr[m * 7 + of][j] + db_s[ot * 112 + o_loc];
                        float ya = __ldg(&yt[o_loc * 128 + n_loc]);
                        float sp = fmaxf(x, 0.f) + __logf(1.f + __expf(-fabsf(x)));
                        acc[m][j >> 1] += ya * fminf(sp - x, 100.f) + (1.f - ya) * fminf(sp, 100.f);
                        cfr[m * 7 + of][j] = 0.f;
                    }
            ot++; s = 0;
        } else {
            s++;
        }
    }
#pragma unroll
    for (int m = 0; m < 2; m++)
#pragma unroll
        for (int r = 0; r < 2; r++) {
            float v = acc[m][r];
            v += __shfl_xor_sync(0xffffffffu, v, 1);
            v += __shfl_xor_sync(0xffffffffu, v, 2);
            if (lc == 0) atomicAdd(&red[wn * 32 + 16 * m + 8 * r + lr], v);
        }
    __syncthreads();
    if (tid < 128) g_logb[(n0 + tid) * 16 + k] = -red[tid] * 0.01f;
}

// ============================================================================
// Kernel E: HMM fwd/bwd concurrent + gamma.
// ============================================================================
__global__ __launch_bounds__(512) void k_hmm(const float* __restrict__ log_pi,
                                             const float* __restrict__ log_A,
                                             float* __restrict__ out) {
    __shared__ float lbs[2048];
    __shared__ float sA[256];
    __shared__ float lp[16];
    __shared__ float as_[2048];
    __shared__ float bs_[2048];
    __shared__ float p0[16], p1[16], q0[16], q1[16];
    const int b = blockIdx.x;
    const int tid = threadIdx.x;
    const unsigned FULL = 0xffffffffu;

#pragma unroll
    for (int ii = 0; ii < 4; ii++) {
        int idx = tid + ii * 512;
        lbs[idx] = g_logb[b * 2048 + idx];
    }
    if (tid < 256) {
        float v = log_A[tid];
        float m = v;
#pragma unroll
        for (int mk = 8; mk >= 1; mk >>= 1) m = fmaxf(m, __shfl_xor_sync(FULL, m, mk));
        float e = __expf(v - m);
        float s = e;
#pragma unroll
        for (int mk = 8; mk >= 1; mk >>= 1) s += __shfl_xor_sync(FULL, s, mk);
        sA[tid] = __logf(e / s + 1e-9f);
    }
    if (tid < 16) {
        float v = log_pi[tid];
        float m = v;
#pragma unroll
        for (int mk = 8; mk >= 1; mk >>= 1) m = fmaxf(m, __shfl_xor_sync(0xffffu, m, mk));
        float e = __expf(v - m);
        float s = e;
#pragma unroll
        for (int mk = 8; mk >= 1; mk >>= 1) s += __shfl_xor_sync(0xffffu, s, mk);
        lp[tid] = __logf(e / s + 1e-9f);
    }
    __syncthreads();
    if (tid < 16) {
        float a = lp[tid] + lbs[tid];
        as_[tid] = a;
        p0[tid] = a;
    }
    if (tid >= 256 && tid < 272) {
        bs_[127 * 16 + (tid - 256)] = 0.f;
        q1[tid - 256] = 0.f;
    }
    __syncthreads();
    if (tid < 256) {
        const int k = tid >> 4, j = tid & 15;
        for (int t = 1; t < 128; t++) {
            const float* src = (t & 1) ? p0 : p1;
            float* dst = (t & 1) ? p1 : p0;
            float v = src[j] + sA[j * 16 + k];
            float m = v;
#pragma unroll
            for (int mk = 8; mk >= 1; mk >>= 1) m = fmaxf(m, __shfl_xor_sync(FULL, m, mk));
            float e = __expf(v - m);
            float s = e;
#pragma unroll
            for (int mk = 8; mk >= 1; mk >>= 1) s += __shfl_xor_sync(FULL, s, mk);
            float cur = m + __logf(s) + lbs[t * 16 + k];
            if (j == 0) { as_[t * 16 + k] = cur; dst[k] = cur; }
            asm volatile("bar.sync 1, 256;" ::: "memory");
        }
    } else {
        const int tid2 = tid - 256;
        const int j = tid2 >> 4, k = tid2 & 15;
        for (int t = 126; t >= 0; t--) {
            const float* src = ((t + 1) & 1) ? q1 : q0;
            float* dst = (t & 1) ? q1 : q0;
            float v = sA[j * 16 + k] + lbs[(t + 1) * 16 + k] + src[k];
            float m = v;
#pragma unroll
            for (int mk = 8; mk >= 1; mk >>= 1) m = fmaxf(m, __shfl_xor_sync(FULL, m, mk));
            float e = __expf(v - m);
            float s = e;
#pragma unroll
            for (int mk = 8; mk >= 1; mk >>= 1) s += __shfl_xor_sync(FULL, s, mk);
            float cur = m + __logf(s);
            if (k == 0) { bs_[t * 16 + j] = cur; dst[j] = cur; }
            asm volatile("bar.sync 2, 256;" ::: "memory");
        }
    }
    __syncthreads();
#pragma unroll
    for (int ii = 0; ii < 4; ii++) {
        int idx = tid + ii * 512;
        g_la[b * 2048 + idx] = as_[idx];
        g_lbeta[b * 2048 + idx] = bs_[idx];
    }
    if (tid < 128) {
        int t = tid;
        float lg[16];
        float m = -1e30f;
#pragma unroll
        for (int kk = 0; kk < 16; kk++) {
            lg[kk] = as_[t * 16 + kk] + bs_[t * 16 + kk];
            m = fmaxf(m, lg[kk]);
        }
        float s = 0.f;
#pragma unroll
        for (int kk = 0; kk < 16; kk++) s += __expf(lg[kk] - m);
        float l = m + __logf(s);
#pragma unroll
        for (int kk = 0; kk < 16; kk++) out[b * 2048 + t * 16 + kk] = __expf(lg[kk] - l);
    }
}

// ============================================================================
// Kernel F: xi. grid (16, 32), block 256; each block does 8 t values.
// ============================================================================
__global__ __launch_bounds__(256) void k_xi(const float* __restrict__ log_A,
                                            float* __restrict__ out) {
    __shared__ float sA[256];
    __shared__ float wm[8], ws[8];
    const int b = blockIdx.y;
    const int tid = threadIdx.x;
    const int j = tid >> 4, k = tid & 15;
    const unsigned FULL = 0xffffffffu;
    {
        float v = log_A[tid];
        float m = v;
#pragma unroll
        for (int mk = 8; mk >= 1; mk >>= 1) m = fmaxf(m, __shfl_xor_sync(FULL, m, mk));
        float e = __expf(v - m);
        float s = e;
#pragma unroll
        for (int mk = 8; mk >= 1; mk >>= 1) s += __shfl_xor_sync(FULL, s, mk);
        sA[tid] = __logf(e / s + 1e-9f);
    }
    __syncthreads();
    const float sAv = sA[tid];
    for (int tt = 0; tt < 8; tt++) {
        const int t = blockIdx.x * 8 + tt;
        if (t >= 127) break;
        const int nt = b * 128 + t;
        float v = g_la[nt * 16 + j] + sAv + g_logb[(nt + 1) * 16 + k] + g_lbeta[(nt + 1) * 16 + k];
        float m = v;
#pragma unroll
        for (int mk = 16; mk >= 1; mk >>= 1) m = fmaxf(m, __shfl_xor_sync(FULL, m, mk));
        if ((tid & 31) == 0) wm[tid >> 5] = m;
        __syncthreads();
        float M = wm[0];
#pragma unroll
        for (int w = 1; w < 8; w++) M = fmaxf(M, wm[w]);
        float e = __expf(v - M);
        float s = e;
#pragma unroll
        for (int mk = 16; mk >= 1; mk >>= 1) s += __shfl_xor_sync(FULL, s, mk);
        if ((tid & 31) == 0) ws[tid >> 5] = s;
        __syncthreads();
        float S = 0.f;
#pragma unroll
        for (int w = 0; w < 8; w++) S += ws[w];
        out[65536 + (b * 127 + t) * 256 + tid] = __expf(v - M - __logf(S));
        __syncthreads();
    }
}

// ============================================================================
extern "C" void kernel_launch(void* const* d_in, const int* in_sizes, int n_in,
                              void* d_out, int out_size) {
    const float* y   = (const float*)d_in[0];
    const float* w1  = (const float*)d_in[1];
    const float* b1  = (const float*)d_in[2];
    const float* w2  = (const float*)d_in[3];
    const float* b2  = (const float*)d_in[4];
    const float* fcw = (const float*)d_in[5];
    const float* fcb = (const float*)d_in[6];
    const float* dw  = (const float*)d_in[7];
    const float* db  = (const float*)d_in[8];
    const float* lpi = (const float*)d_in[9];
    const float* lA  = (const float*)d_in[10];
    const float* eps = (const float*)d_in[11];
    float* out = (float*)d_out;

    static int attr_done = 0;
    if (!attr_done) {
        cudaFuncSetAttribute(k_dec_mma, cudaFuncAttributeMaxDynamicSharedMemorySize, DEC_SMEM);
        attr_done = 1;
    }

    k_pack<<<DW_BLOCKS + 224, 256>>>(dw, y);
    k_enc1<<<dim3(32, 7), 256>>>(y, w1, b1);
    k_enc2<<<64, 256>>>(w2, b2, fcw, fcb, eps);
    k_dec_mma<<<dim3(32, 16), 256, DEC_SMEM>>>(fcw, db);
    k_hmm<<<32, 512>>>(lpi, lA, out);
    k_xi<<<dim3(16, 32), 256>>>(lA, out);
}

// round 6
// speedup vs baseline: 3.5275x; 1.0946x over previous
#include <cuda_runtime.h>
#include <cuda_bf16.h>
#include <stdint.h>

// HMM-VAE fused pipeline. enc1 on tf32 mma.sync, decoder on bf16 mma.sync
// (ldmatrix + depth-2 cp.async pipeline, 512 threads / 16 warps per block).
// B=32, T=128, N=4096, K=16, L=16, D=784, H=400.

#define N_TOT 4096

// -------- scratch --------
__device__ float g_H[N_TOT * 400];
__device__ float g_base[N_TOT * 400];
__device__ float g_logb[N_TOT * 16];
__device__ float g_la[N_TOT * 16];
__device__ float g_lbeta[N_TOT * 16];
__device__ uint4 g_dwb[49 * 1008];           // dec_w bf16 slabs [ot*7+s][112 o][72 half]
__device__ float g_yt[32 * 7 * 112 * 128];   // y transposed tiles [nt][ot][o][n]

// ======================= helpers =======================
static __device__ __forceinline__ uint32_t smem_u32(const void* p) {
    uint32_t a;
    asm("{ .reg .u64 t; cvta.to.shared.u64 t, %1; cvt.u32.u64 %0, t; }" : "=r"(a) : "l"(p));
    return a;
}
static __device__ __forceinline__ void cp_async16(uint32_t saddr, const void* g) {
    asm volatile("cp.async.cg.shared.global [%0], [%1], 16;" :: "r"(saddr), "l"(g));
}
static __device__ __forceinline__ void cp_commit() {
    asm volatile("cp.async.commit_group;" ::: "memory");
}
static __device__ __forceinline__ void cp_wait0() {
    asm volatile("cp.async.wait_group 0;" ::: "memory");
}
static __device__ __forceinline__ void cp_wait1() {
    asm volatile("cp.async.wait_group 1;" ::: "memory");
}
static __device__ __forceinline__ void ldsm_x4(uint32_t& r0, uint32_t& r1, uint32_t& r2,
                                               uint32_t& r3, uint32_t addr) {
    asm volatile("ldmatrix.sync.aligned.m8n8.x4.shared.b16 {%0,%1,%2,%3}, [%4];"
                 : "=r"(r0), "=r"(r1), "=r"(r2), "=r"(r3) : "r"(addr));
}
static __device__ __forceinline__ void ldsm_x2(uint32_t& r0, uint32_t& r1, uint32_t addr) {
    asm volatile("ldmatrix.sync.aligned.m8n8.x2.shared.b16 {%0,%1}, [%2];"
                 : "=r"(r0), "=r"(r1) : "r"(addr));
}
static __device__ __forceinline__ void mma16816(float* c, const uint32_t* a, const uint32_t* b) {
    asm volatile(
        "mma.sync.aligned.m16n8k16.row.col.f32.bf16.bf16.f32 "
        "{%0,%1,%2,%3}, {%4,%5,%6,%7}, {%8,%9}, {%0,%1,%2,%3};"
        : "+f"(c[0]), "+f"(c[1]), "+f"(c[2]), "+f"(c[3])
        : "r"(a[0]), "r"(a[1]), "r"(a[2]), "r"(a[3]), "r"(b[0]), "r"(b[1]));
}
static __device__ __forceinline__ void mma1688_tf32(float* c, const uint32_t* a, const uint32_t* b) {
    asm volatile(
        "mma.sync.aligned.m16n8k8.row.col.f32.tf32.tf32.f32 "
        "{%0,%1,%2,%3}, {%4,%5,%6,%7}, {%8,%9}, {%0,%1,%2,%3};"
        : "+f"(c[0]), "+f"(c[1]), "+f"(c[2]), "+f"(c[3])
        : "r"(a[0]), "r"(a[1]), "r"(a[2]), "r"(a[3]), "r"(b[0]), "r"(b[1]));
}
static __device__ __forceinline__ uint32_t to_tf32(float f) {
    uint32_t r;
    asm("cvt.rna.tf32.f32 %0, %1;" : "=r"(r) : "f"(f));
    return r;
}
static __device__ __forceinline__ uint32_t pack_bf16x2(float a, float b) {
    __nv_bfloat162 t = __floats2bfloat162_rn(a, b);
    return *reinterpret_cast<uint32_t*>(&t);
}

// ============================================================================
// pack kernel: dec_w bf16 slabs + y transpose (merged)
// ============================================================================
#define DW_BLOCKS 1544   // ceil(49*112*72/256)
__global__ __launch_bounds__(256) void k_pack(const float* __restrict__ dw,
                                              const float* __restrict__ y) {
    __shared__ float sm[64 * 113];
    const int bid = blockIdx.x, tid = threadIdx.x;
    if (bid < DW_BLOCKS) {
        int idx = bid * 256 + tid;
        if (idx < 49 * 112 * 72) {
            int slabIdx = idx / 8064, rem = idx % 8064;
            int o = rem / 72, c = rem % 72;
            int ot = slabIdx / 7, s = slabIdx % 7;
            int h = s * 64 + c;
            float v = (c < 64 && h < 400) ? dw[(ot * 112 + o) * 400 + h] : 0.f;
            ((__nv_bfloat16*)g_dwb)[idx] = __float2bfloat16(v);
        }
        return;
    }
    const int b2 = bid - DW_BLOCKS;
    const int nt = b2 / 7, ot = b2 % 7;
    float* outb = g_yt + (nt * 7 + ot) * 14336;
    for (int half = 0; half < 2; half++) {
        int nb = nt * 128 + half * 64;
        for (int idx = tid; idx < 64 * 112; idx += 256) {
            int nl = idx / 112, c = idx % 112;
            sm[nl * 113 + c] = y[(nb + nl) * 784 + ot * 112 + c];
        }
        __syncthreads();
        for (int idx = tid; idx < 112 * 64; idx += 256) {
            int c = idx >> 6, nl = idx & 63;
            outb[c * 128 + half * 64 + nl] = sm[nl * 113 + c];
        }
        __syncthreads();
    }
}

// ============================================================================
// Kernel A: H = relu(Y @ W1^T + b1) on tf32 mma.sync.
// ============================================================================
__global__ __launch_bounds__(256) void k_enc1(const float* __restrict__ y,
                                              const float* __restrict__ w1,
                                              const float* __restrict__ b1) {
    __shared__ __align__(16) float As[2][128 * 20];
    __shared__ __align__(16) float Bs[2][64 * 20];
    const int tid = threadIdx.x, wid = tid >> 5, lane = tid & 31;
    const int wn = wid & 3, wo = wid >> 2;
    const int lr = lane >> 2, lc = lane & 3;
    const int n0 = blockIdx.x * 128;
    const int h0 = blockIdx.y * 64;
    const int vrows = (400 - h0) < 64 ? (400 - h0) : 64;

    const uint32_t aB = smem_u32(As);
    const uint32_t bB = smem_u32(Bs);

    if (vrows < 64) {
        for (int i = tid; i < 2 * 64 * 20; i += 256) {
            int r = (i % (64 * 20)) / 20;
            if (r >= vrows) ((float*)Bs)[i] = 0.f;
        }
        __syncthreads();
    }

    auto loadA = [&](int buf, int c0) {
        for (int it = tid; it < 512; it += 256) {
            int row = it >> 2, seg = it & 3;
            cp_async16(aB + (buf * 128 * 20 + row * 20 + seg * 4) * 4,
                       y + (size_t)(n0 + row) * 784 + c0 + seg * 4);
        }
    };
    auto loadB = [&](int buf, int c0) {
        for (int it = tid; it < vrows * 4; it += 256) {
            int row = it >> 2, seg = it & 3;
            cp_async16(bB + (buf * 64 * 20 + row * 20 + seg * 4) * 4,
                       w1 + (size_t)(h0 + row) * 784 + c0 + seg * 4);
        }
    };
    loadA(0, 0); loadB(0, 0); cp_commit();

    float acc[2][4][4];
#pragma unroll
    for (int m = 0; m < 2; m++)
#pragma unroll
        for (int o = 0; o < 4; o++)
#pragma unroll
            for (int j = 0; j < 4; j++) acc[m][o][j] = 0.f;

    for (int ch = 0; ch < 49; ch++) {
        const int buf = ch & 1;
        cp_wait0();
        __syncthreads();
        if (ch < 48) {
            loadA(buf ^ 1, (ch + 1) * 16);
            loadB(buf ^ 1, (ch + 1) * 16);
            cp_commit();
        }
        const float* Ab = As[buf];
        const float* Bb = Bs[buf];
#pragma unroll
        for (int ks = 0; ks < 2; ks++) {
            const int kk = ks * 8;
            uint32_t afr[2][4];
#pragma unroll
            for (int m = 0; m < 2; m++) {
                int r = wn * 32 + m * 16 + lr;
                afr[m][0] = to_tf32(Ab[r * 20 + kk + lc]);
                afr[m][1] = to_tf32(Ab[(r + 8) * 20 + kk + lc]);
                afr[m][2] = to_tf32(Ab[r * 20 + kk + lc + 4]);
                afr[m][3] = to_tf32(Ab[(r + 8) * 20 + kk + lc + 4]);
            }
#pragma unroll
            for (int o = 0; o < 4; o++) {
                int br = wo * 32 + o * 8 + lr;
                uint32_t bfr[2];
                bfr[0] = to_tf32(Bb[br * 20 + kk + lc]);
                bfr[1] = to_tf32(Bb[br * 20 + kk + lc + 4]);
#pragma unroll
                for (int m = 0; m < 2; m++) mma1688_tf32(acc[m][o], afr[m], bfr);
            }
        }
    }
#pragma unroll
    for (int m = 0; m < 2; m++)
#pragma unroll
        for (int o = 0; o < 4; o++)
#pragma unroll
            for (int j = 0; j < 4; j++) {
                int h = h0 + wo * 32 + o * 8 + lc * 2 + (j & 1);
                int n = n0 + wn * 32 + m * 16 + lr + 8 * (j >> 1);
                if (h < 400)
                    g_H[n * 400 + h] = fmaxf(acc[m][o][j] + __ldg(&b1[h]), 0.f);
            }
}

// ============================================================================
// Kernel BC: enc2 (mu/lv GEMM) + z + base GEMM
// ============================================================================
__global__ __launch_bounds__(256) void k_enc2(const float* __restrict__ w2,
                                              const float* __restrict__ b2,
                                              const float* __restrict__ fcw,
                                              const float* __restrict__ fcb,
                                              const float* __restrict__ eps) {
    __shared__ float Asm[64 * 17];
    __shared__ float Bsm[32 * 17];
    __shared__ float zs[64 * 16];
    const int tid = threadIdx.x;
    const int ty = tid >> 4, tx = tid & 15;
    const int n0 = blockIdx.x * 64;

    float amu[4] = {0.f, 0.f, 0.f, 0.f};
    float alv[4] = {0.f, 0.f, 0.f, 0.f};

    for (int ch = 0; ch < 25; ch++) {
        const int k0 = ch * 16;
        for (int i = tid; i < 64 * 16; i += 256) {
            int r = i >> 4, c = i & 15;
            Asm[r * 17 + c] = g_H[(n0 + r) * 400 + k0 + c];
        }
        for (int i = tid; i < 32 * 16; i += 256) {
            int r = i >> 4, c = i & 15;
            Bsm[r * 17 + c] = w2[r * 400 + k0 + c];
        }
        __syncthreads();
#pragma unroll
        for (int c = 0; c < 16; c++) {
            float bmu = Bsm[tx * 17 + c];
            float blv = Bsm[(tx + 16) * 17 + c];
#pragma unroll
            for (int i = 0; i < 4; i++) {
                float a = Asm[(ty * 4 + i) * 17 + c];
                amu[i] = fmaf(a, bmu, amu[i]);
                alv[i] = fmaf(a, blv, alv[i]);
            }
        }
        __syncthreads();
    }
    const float bm = b2[tx], bl = b2[tx + 16];
#pragma unroll
    for (int i = 0; i < 4; i++) {
        int n = ty * 4 + i;
        float mu = amu[i] + bm;
        float lv = alv[i] + bl;
        float z = mu + eps[(n0 + n) * 16 + tx] * __expf(0.5f * lv);
        zs[n * 16 + tx] = z;
    }
    __syncthreads();
    float w0[16], w1r[16], fb0 = 0.f, fb1 = 0.f;
    const int h0i = tid, h1i = tid + 256;
    {
        const float4* p = (const float4*)&fcw[h0i * 32];
#pragma unroll
        for (int q = 0; q < 4; q++) {
            float4 v = p[q];
            w0[q * 4 + 0] = v.x; w0[q * 4 + 1] = v.y; w0[q * 4 + 2] = v.z; w0[q * 4 + 3] = v.w;
        }
        fb0 = fcb[h0i];
    }
    if (h1i < 400) {
        const float4* p = (const float4*)&fcw[h1i * 32];
#pragma unroll
        for (int q = 0; q < 4; q++) {
            float4 v = p[q];
            w1r[q * 4 + 0] = v.x; w1r[q * 4 + 1] = v.y; w1r[q * 4 + 2] = v.z; w1r[q * 4 + 3] = v.w;
        }
        fb1 = fcb[h1i];
    }
    for (int n = 0; n < 64; n++) {
        float zr[16];
#pragma unroll
        for (int l = 0; l < 16; l++) zr[l] = zs[n * 16 + l];
        float s0 = fb0, s1 = fb1;
#pragma unroll
        for (int l = 0; l < 16; l++) {
            s0 = fmaf(zr[l], w0[l], s0);
            if (h1i < 400) s1 = fmaf(zr[l], w1r[l], s1);
        }
        g_base[(n0 + n) * 400 + h0i] = s0;
        if (h1i < 400) g_base[(n0 + n) * 400 + h1i] = s1;
    }
}

// ============================================================================
// Kernel D: decoder GEMM (bf16 mma.sync + ldmatrix) + fused BCE.
// grid (32, 16), 512 threads (16 warps: 8n x 2o), warp tile 16n x 56o.
// hk bf16 [128][456h] + 3 dec_w slab bufs [112][72h].
// ============================================================================
#define BSLAB_B    16128
#define HK_BYTES   116736
#define DEC_SMEM   (HK_BYTES + 3 * BSLAB_B + 448 * 4 + 784 * 4 + 128 * 4)

__global__ __launch_bounds__(512) void k_dec_mma(const float* __restrict__ fcw,
                                                 const float* __restrict__ db) {
    extern __shared__ __align__(16) char smem[];
    uint32_t* const hk32 = (uint32_t*)smem;
    float* const wxs  = (float*)(smem + HK_BYTES + 3 * BSLAB_B);
    float* const db_s = wxs + 448;
    float* const red  = db_s + 784;
    const uint32_t hkB = smem_u32(smem);
    const uint32_t bB = hkB + HK_BYTES;

    const int tid = threadIdx.x, wid = tid >> 5, lane = tid & 31;
    const int wn = wid & 7, wo = wid >> 3;
    const int nt = blockIdx.x, k = blockIdx.y;
    const int n0 = nt * 128;
    const int lr = lane >> 2, lc = lane & 3;

    for (int h = tid; h < 448; h += 512) wxs[h] = (h < 400) ? fcw[h * 32 + 16 + k] : 0.f;
    for (int o = tid; o < 784; o += 512) db_s[o] = db[o];
    if (tid < 128) red[tid] = 0.f;
    __syncthreads();

    // ---- build hk bf16: hk[n][h] = relu(base[n0+n][h] + wx[h]) ----
    for (int idx = tid; idx < 128 * 200; idx += 512) {
        int n = idx / 200, w = idx % 200;
        const float2 bv = *(const float2*)&g_base[(n0 + n) * 400 + 2 * w];
        float v0 = fmaxf(bv.x + wxs[2 * w], 0.f);
        float v1 = fmaxf(bv.y + wxs[2 * w + 1], 0.f);
        hk32[n * 228 + w] = pack_bf16x2(v0, v1);
    }

    // prefetch slabs 0 and 1 (separate commit groups)
    for (int it = tid; it < 1008; it += 512) cp_async16(bB + it * 16, g_dwb + it);
    cp_commit();
    for (int it = tid; it < 1008; it += 512) cp_async16(bB + BSLAB_B + it * 16, g_dwb + 1008 + it);
    cp_commit();

    // ---- per-lane ldmatrix base addresses ----
    // A: warp owns 16 rows starting wn*16; x4 covers rows 0-15 x k16
    const uint32_t aBase = hkB + (uint32_t)(wn * 16 + (lane & 15)) * 912 + ((lane >> 4) << 4);
    // B: warp owns 56 o-rows starting wo*56
    const int bq = lane >> 3;
    const uint32_t bLane = (uint32_t)(wo * 56 + (lane & 7) + (bq >> 1) * 8) * 144 + (bq & 1) * 16;

    float cfr[7][4];
#pragma unroll
    for (int f = 0; f < 7; f++)
#pragma unroll
        for (int j = 0; j < 4; j++) cfr[f][j] = 0.f;
    float acc[2] = {0.f, 0.f};

    int ot = 0, s = 0;
    for (int i = 0; i < 49; i++) {
        if (i < 48) cp_wait1(); else cp_wait0();
        __syncthreads();
        if (i + 2 < 49) {
            const uint4* src = g_dwb + (i + 2) * 1008;
            const uint32_t dsta = bB + ((i + 2) % 3) * BSLAB_B;
            for (int it = tid; it < 1008; it += 512) cp_async16(dsta + it * 16, src + it);
            cp_commit();
        }
        // ---- MMA over slab i (buf i%3) ----
        const int nks = (s == 6) ? 1 : 4;
        const uint32_t aS = aBase + s * 128;
        const uint32_t bS = bB + (i % 3) * BSLAB_B + bLane;
        for (int ks = 0; ks < nks; ks++) {
            const uint32_t aAddr = aS + ks * 32;
            const uint32_t bAddr = bS + ks * 32;
            uint32_t A0[4];
            ldsm_x4(A0[0], A0[1], A0[2], A0[3], aAddr);
#pragma unroll
            for (int p = 0; p < 3; p++) {
                uint32_t b0, b1, b2, b3;
                ldsm_x4(b0, b1, b2, b3, bAddr + p * 2304);
                uint32_t bb0[2] = {b0, b1};
                uint32_t bb1[2] = {b2, b3};
                mma16816(cfr[2 * p], A0, bb0);
                mma16816(cfr[2 * p + 1], A0, bb1);
            }
            {
                uint32_t b0, b1;
                ldsm_x2(b0, b1, bAddr + 3 * 2304);
                uint32_t bb[2] = {b0, b1};
                mma16816(cfr[6], A0, bb);
            }
        }
        // ---- end of ot: fused BCE epilogue ----
        if (s == 6) {
            const float* yt = g_yt + (nt * 7 + ot) * 14336;
#pragma unroll
            for (int of = 0; of < 7; of++)
#pragma unroll
                for (int j = 0; j < 4; j++) {
                    int o_loc = wo * 56 + 8 * of + lc * 2 + (j & 1);
                    int n_loc = wn * 16 + lr + 8 * (j >> 1);
                    float x = cfr[of][j] + db_s[ot * 112 + o_loc];
                    float ya = __ldg(&yt[o_loc * 128 + n_loc]);
                    float sp = fmaxf(x, 0.f) + __logf(1.f + __expf(-fabsf(x)));
                    acc[j >> 1] += ya * fminf(sp - x, 100.f) + (1.f - ya) * fminf(sp, 100.f);
                    cfr[of][j] = 0.f;
                }
            ot++; s = 0;
        } else {
            s++;
        }
    }
    // reduce over lc (o-quads within warp), then across the two o-warps
#pragma unroll
    for (int r = 0; r < 2; r++) {
        float v = acc[r];
        v += __shfl_xor_sync(0xffffffffu, v, 1);
        v += __shfl_xor_sync(0xffffffffu, v, 2);
        if (lc == 0) atomicAdd(&red[wn * 16 + 8 * r + lr], v);
    }
    __syncthreads();
    if (tid < 128) g_logb[(n0 + tid) * 16 + k] = -red[tid] * 0.01f;
}

// ============================================================================
// Kernel E: HMM fwd/bwd concurrent + gamma.
// ============================================================================
__global__ __launch_bounds__(512) void k_hmm(const float* __restrict__ log_pi,
                                             const float* __restrict__ log_A,
                                             float* __restrict__ out) {
    __shared__ float lbs[2048];
    __shared__ float sA[256];
    __shared__ float lp[16];
    __shared__ float as_[2048];
    __shared__ float bs_[2048];
    __shared__ float p0[16], p1[16], q0[16], q1[16];
    const int b = blockIdx.x;
    const int tid = threadIdx.x;
    const unsigned FULL = 0xffffffffu;

#pragma unroll
    for (int ii = 0; ii < 4; ii++) {
        int idx = tid + ii * 512;
        lbs[idx] = g_logb[b * 2048 + idx];
    }
    if (tid < 256) {
        float v = log_A[tid];
        float m = v;
#pragma unroll
        for (int mk = 8; mk >= 1; mk >>= 1) m = fmaxf(m, __shfl_xor_sync(FULL, m, mk));
        float e = __expf(v - m);
        float s = e;
#pragma unroll
        for (int mk = 8; mk >= 1; mk >>= 1) s += __shfl_xor_sync(FULL, s, mk);
        sA[tid] = __logf(e / s + 1e-9f);
    }
    if (tid < 16) {
        float v = log_pi[tid];
        float m = v;
#pragma unroll
        for (int mk = 8; mk >= 1; mk >>= 1) m = fmaxf(m, __shfl_xor_sync(0xffffu, m, mk));
        float e = __expf(v - m);
        float s = e;
#pragma unroll
        for (int mk = 8; mk >= 1; mk >>= 1) s += __shfl_xor_sync(0xffffu, s, mk);
        lp[tid] = __logf(e / s + 1e-9f);
    }
    __syncthreads();
    if (tid < 16) {
        float a = lp[tid] + lbs[tid];
        as_[tid] = a;
        p0[tid] = a;
    }
    if (tid >= 256 && tid < 272) {
        bs_[127 * 16 + (tid - 256)] = 0.f;
        q1[tid - 256] = 0.f;
    }
    __syncthreads();
    if (tid < 256) {
        const int k = tid >> 4, j = tid & 15;
        for (int t = 1; t < 128; t++) {
            const float* src = (t & 1) ? p0 : p1;
            float* dst = (t & 1) ? p1 : p0;
            float v = src[j] + sA[j * 16 + k];
            float m = v;
#pragma unroll
            for (int mk = 8; mk >= 1; mk >>= 1) m = fmaxf(m, __shfl_xor_sync(FULL, m, mk));
            float e = __expf(v - m);
            float s = e;
#pragma unroll
            for (int mk = 8; mk >= 1; mk >>= 1) s += __shfl_xor_sync(FULL, s, mk);
            float cur = m + __logf(s) + lbs[t * 16 + k];
            if (j == 0) { as_[t * 16 + k] = cur; dst[k] = cur; }
            asm volatile("bar.sync 1, 256;" ::: "memory");
        }
    } else {
        const int tid2 = tid - 256;
        const int j = tid2 >> 4, k = tid2 & 15;
        for (int t = 126; t >= 0; t--) {
            const float* src = ((t + 1) & 1) ? q1 : q0;
            float* dst = (t & 1) ? q1 : q0;
            float v = sA[j * 16 + k] + lbs[(t + 1) * 16 + k] + src[k];
            float m = v;
#pragma unroll
            for (int mk = 8; mk >= 1; mk >>= 1) m = fmaxf(m, __shfl_xor_sync(FULL, m, mk));
            float e = __expf(v - m);
            float s = e;
#pragma unroll
            for (int mk = 8; mk >= 1; mk >>= 1) s += __shfl_xor_sync(FULL, s, mk);
            float cur = m + __logf(s);
            if (k == 0) { bs_[t * 16 + j] = cur; dst[j] = cur; }
            asm volatile("bar.sync 2, 256;" ::: "memory");
        }
    }
    __syncthreads();
#pragma unroll
    for (int ii = 0; ii < 4; ii++) {
        int idx = tid + ii * 512;
        g_la[b * 2048 + idx] = as_[idx];
        g_lbeta[b * 2048 + idx] = bs_[idx];
    }
    if (tid < 128) {
        int t = tid;
        float lg[16];
        float m = -1e30f;
#pragma unroll
        for (int kk = 0; kk < 16; kk++) {
            lg[kk] = as_[t * 16 + kk] + bs_[t * 16 + kk];
            m = fmaxf(m, lg[kk]);
        }
        float s = 0.f;
#pragma unroll
        for (int kk = 0; kk < 16; kk++) s += __expf(lg[kk] - m);
        float l = m + __logf(s);
#pragma unroll
        for (int kk = 0; kk < 16; kk++) out[b * 2048 + t * 16 + kk] = __expf(lg[kk] - l);
    }
}

// ============================================================================
// Kernel F: xi. grid (16, 32), block 256; each block does 8 t values.
// ============================================================================
__global__ __launch_bounds__(256) void k_xi(const float* __restrict__ log_A,
                                            float* __restrict__ out) {
    __shared__ float sA[256];
    __shared__ float wm[8], ws[8];
    const int b = blockIdx.y;
    const int tid = threadIdx.x;
    const int j = tid >> 4, k = tid & 15;
    const unsigned FULL = 0xffffffffu;
    {
        float v = log_A[tid];
        float m = v;
#pragma unroll
        for (int mk = 8; mk >= 1; mk >>= 1) m = fmaxf(m, __shfl_xor_sync(FULL, m, mk));
        float e = __expf(v - m);
        float s = e;
#pragma unroll
        for (int mk = 8; mk >= 1; mk >>= 1) s += __shfl_xor_sync(FULL, s, mk);
        sA[tid] = __logf(e / s + 1e-9f);
    }
    __syncthreads();
    const float sAv = sA[tid];
    for (int tt = 0; tt < 8; tt++) {
        const int t = blockIdx.x * 8 + tt;
        if (t >= 127) break;
        const int nt = b * 128 + t;
        float v = g_la[nt * 16 + j] + sAv + g_logb[(nt + 1) * 16 + k] + g_lbeta[(nt + 1) * 16 + k];
        float m = v;
#pragma unroll
        for (int mk = 16; mk >= 1; mk >>= 1) m = fmaxf(m, __shfl_xor_sync(FULL, m, mk));
        if ((tid & 31) == 0) wm[tid >> 5] = m;
        __syncthreads();
        float M = wm[0];
#pragma unroll
        for (int w = 1; w < 8; w++) M = fmaxf(M, wm[w]);
        float e = __expf(v - M);
        float s = e;
#pragma unroll
        for (int mk = 16; mk >= 1; mk >>= 1) s += __shfl_xor_sync(FULL, s, mk);
        if ((tid & 31) == 0) ws[tid >> 5] = s;
        __syncthreads();
        float S = 0.f;
#pragma unroll
        for (int w = 0; w < 8; w++) S += ws[w];
        out[65536 + (b * 127 + t) * 256 + tid] = __expf(v - M - __logf(S));
        __syncthreads();
    }
}

// ============================================================================
extern "C" void kernel_launch(void* const* d_in, const int* in_sizes, int n_in,
                              void* d_out, int out_size) {
    const float* y   = (const float*)d_in[0];
    const float* w1  = (const float*)d_in[1];
    const float* b1  = (const float*)d_in[2];
    const float* w2  = (const float*)d_in[3];
    const float* b2  = (const float*)d_in[4];
    const float* fcw = (const float*)d_in[5];
    const float* fcb = (const float*)d_in[6];
    const float* dw  = (const float*)d_in[7];
    const float* db  = (const float*)d_in[8];
    const float* lpi = (const float*)d_in[9];
    const float* lA  = (const float*)d_in[10];
    const float* eps = (const float*)d_in[11];
    float* out = (float*)d_out;

    static int attr_done = 0;
    if (!attr_done) {
        cudaFuncSetAttribute(k_dec_mma, cudaFuncAttributeMaxDynamicSharedMemorySize, DEC_SMEM);
        attr_done = 1;
    }

    k_pack<<<DW_BLOCKS + 224, 256>>>(dw, y);
    k_enc1<<<dim3(32, 7), 256>>>(y, w1, b1);
    k_enc2<<<64, 256>>>(w2, b2, fcw, fcb, eps);
    k_dec_mma<<<dim3(32, 16), 512, DEC_SMEM>>>(fcw, db);
    k_hmm<<<32, 512>>>(lpi, lA, out);
    k_xi<<<dim3(16, 32), 256>>>(lA, out);
}